// round 11
// baseline (speedup 1.0000x reference)
#include <cuda_runtime.h>

#define Bn 64
#define H  384
#define HH (H*H)
#define BORDER 3
#define CROP 378
#define NSH 49

// corr tiling: 3 x 24 tiles exactly partition 384 x 384 (owned 128 x 16 each)
#define TX 128
#define TY 16
#define GX 3
#define GY 24
#define NTILE (GX*GY)   // 72
#define HALO_W 136      // need 134, pad to 136 (16B-safe rows)
#define HALO_H 22       // TY + 6
#define NT 224          // threads per block (7 warps)

// scratch (static device memory; zero-initialized; no allocations anywhere)
__device__ float g_part [Bn*NSH*3*NTILE];   // corr partials: [b][shift][comp][tile]
__device__ float g_rsum [Bn*H*3*3];         // per (b,y,bx): {Sm,SL,Shh} partial
__device__ float g_eL   [Bn*H*3*6];         // left edge cols 0..5 per field
__device__ float g_eR   [Bn*H*3*6];         // right edge cols 378..383 per field
__device__ float g_ppart[Bn*NTILE];         // per-tile sum of pred
__device__ float g_bmin [Bn];               // per-batch min cMSE
__device__ int   g_bctr [Bn];               // per-batch tile counter (self-resets)
__device__ int   g_ctr;                     // global batch counter (self-resets)

// ---------------------------------------------------------------------------
// corr_kernel: three 7x7 correlations + fused box partials; the LAST block of
// each batch (per-batch counter) runs the whole mse finalization inline, and
// the overall-last finalizer reduces the batch minima to the output scalar.
// ---------------------------------------------------------------------------
__global__ __launch_bounds__(NT) void corr_kernel(
    const float* __restrict__ sr, const float* __restrict__ hr,
    const float* __restrict__ mk, float* __restrict__ out)
{
    __shared__ __align__(16) float s_m [HALO_H*HALO_W];
    __shared__ __align__(16) float s_mh[HALO_H*HALO_W];
    __shared__ __align__(16) float s_p [TY*TX];
    __shared__ __align__(16) float s_pp[TY*TX];
    __shared__ float s_red[8];
    // finalizer scratch (used only after main phase; fits under 48KB total)
    __shared__ float sA[24][9];
    __shared__ float sL[12][18];
    __shared__ float sR[12][18];
    __shared__ float Tq[9], GL[18], GR[18];
    __shared__ float eRaw[12][45];   // [r][0..8 rsum | 9..26 eL | 27..44 eR]
    __shared__ float e_w[12][3][7];
    __shared__ float ctot[3][7];
    __shared__ float ssp;
    __shared__ float s_mse[64];
    __shared__ int   s_flag[2];      // [0]=is_batch_finalizer, [1]=is_last

    const int batch = blockIdx.z;
    const int bxi = blockIdx.x, byi = blockIdx.y;
    const int x0 = bxi * TX;
    const int y0 = byi * TY;
    const float* mb = mk + (size_t)batch*HH;
    const float* hb = hr + (size_t)batch*HH;
    const float* sb = sr + (size_t)batch*HH;
    const int tid  = threadIdx.x;
    const int wid  = tid >> 5;
    const int lane = tid & 31;

    // ---- halo tiles of m and m*h via float4 (rows 22, 34 float4 cols) ----
    for (int idx = tid; idx < HALO_H*34; idx += NT) {
        const int r  = idx / 34, c4 = idx % 34;
        const int y  = y0 + r, x = x0 + c4*4;
        float4 m4 = make_float4(0.f,0.f,0.f,0.f);
        float4 h4 = make_float4(0.f,0.f,0.f,0.f);
        if (y < H && x + 3 < H) {
            m4 = *(const float4*)&mb[y*H + x];
            h4 = *(const float4*)&hb[y*H + x];
            if (c4 == 33) { m4.z = 0.f; m4.w = 0.f; }   // cols 134,135 are pad
        }
        float4 l4;
        l4.x = m4.x*h4.x; l4.y = m4.y*h4.y; l4.z = m4.z*h4.z; l4.w = m4.w*h4.w;
        *(float4*)&s_m [r*HALO_W + c4*4] = m4;
        *(float4*)&s_mh[r*HALO_W + c4*4] = l4;
    }
    __syncthreads();

    // ---- fused box partials from owned 16x128 region ----
    for (int r = wid; r < TY; r += 7) {
        const float4 m4 = *(const float4*)&s_m [r*HALO_W + lane*4];
        const float4 l4 = *(const float4*)&s_mh[r*HALO_W + lane*4];
        float sm = m4.x + m4.y + m4.z + m4.w;
        float sl = l4.x + l4.y + l4.z + l4.w;
        float sh = l4.x*l4.x + l4.y*l4.y + l4.z*l4.z + l4.w*l4.w;  // m*h^2 (m binary)
        #pragma unroll
        for (int off = 16; off; off >>= 1) {
            sm += __shfl_xor_sync(0xffffffffu, sm, off);
            sl += __shfl_xor_sync(0xffffffffu, sl, off);
            sh += __shfl_xor_sync(0xffffffffu, sh, off);
        }
        if (lane == 0) {
            float* q = g_rsum + (((size_t)batch*H + (y0+r))*3 + bxi)*3;
            q[0] = sm; q[1] = sl; q[2] = sh;
        }
    }
    if (bxi == 0 && tid < 96) {
        const int r = tid / 6, c = tid % 6;
        const float m = s_m[r*HALO_W + c], l = s_mh[r*HALO_W + c];
        float* q = g_eL + ((size_t)batch*H + (y0+r))*18;
        q[0*6+c] = m; q[1*6+c] = l; q[2*6+c] = l*l;
    }
    if (bxi == 2 && tid < 96) {
        const int r = tid / 6, c = tid % 6;
        const float m = s_m[r*HALO_W + 122 + c], l = s_mh[r*HALO_W + 122 + c];
        float* q = g_eR + ((size_t)batch*H + (y0+r))*18;
        q[0*6+c] = m; q[1*6+c] = l; q[2*6+c] = l*l;
    }

    // ---- pred tile from sr (global) * mask (smem); accumulate sum(pred) ----
    float tp = 0.f;
    for (int idx = tid; idx < TY*TX; idx += NT) {
        const int r = idx >> 7, c = idx & 127;
        const int y = y0 + r, x = x0 + c;   // pred (crop) coordinates
        float p = 0.f;
        if (y < CROP && x < CROP)
            p = sb[(y+BORDER)*H + (x+BORDER)] * s_m[(r+BORDER)*HALO_W + (c+BORDER)];
        s_p[idx] = p; s_pp[idx] = p*p;
        tp += p;
    }
    #pragma unroll
    for (int off = 16; off; off >>= 1)
        tp += __shfl_xor_sync(0xffffffffu, tp, off);
    if (lane == 0) s_red[wid] = tp;
    __syncthreads();
    if (tid == 0) {
        float s = 0.f;
        #pragma unroll
        for (int k = 0; k < 7; k++) s += s_red[k];
        g_ppart[(size_t)batch*NTILE + byi*GX + bxi] = s;
    }

    // ---- main correlation loop (R1-proven scalar core) ----
    const int cb = lane * 4;
    float a_hp[7], a_pp[7], a_mp[7];
    #pragma unroll
    for (int j = 0; j < 7; j++) { a_hp[j]=0.f; a_pp[j]=0.f; a_mp[j]=0.f; }

    for (int r = 0; r < TY; r++) {
        const float4 p4 = *(const float4*)&s_p [r*TX + cb];
        const float4 q4 = *(const float4*)&s_pp[r*TX + cb];
        const float pv[4] = {p4.x, p4.y, p4.z, p4.w};
        const float qv[4] = {q4.x, q4.y, q4.z, q4.w};

        const int hbase = (r + wid)*HALO_W + cb;
        float mw[10], hw[10];
        {
            float4 t; float2 u;
            t = *(const float4*)&s_m[hbase];    mw[0]=t.x; mw[1]=t.y; mw[2]=t.z; mw[3]=t.w;
            t = *(const float4*)&s_m[hbase+4];  mw[4]=t.x; mw[5]=t.y; mw[6]=t.z; mw[7]=t.w;
            u = *(const float2*)&s_m[hbase+8];  mw[8]=u.x; mw[9]=u.y;
            t = *(const float4*)&s_mh[hbase];   hw[0]=t.x; hw[1]=t.y; hw[2]=t.z; hw[3]=t.w;
            t = *(const float4*)&s_mh[hbase+4]; hw[4]=t.x; hw[5]=t.y; hw[6]=t.z; hw[7]=t.w;
            u = *(const float2*)&s_mh[hbase+8]; hw[8]=u.x; hw[9]=u.y;
        }
        #pragma unroll
        for (int j = 0; j < 7; j++) {
            #pragma unroll
            for (int k = 0; k < 4; k++) {
                a_hp[j] = fmaf(hw[j+k], pv[k], a_hp[j]);
                a_mp[j] = fmaf(mw[j+k], pv[k], a_mp[j]);
                a_pp[j] = fmaf(mw[j+k], qv[k], a_pp[j]);
            }
        }
    }

    #pragma unroll
    for (int j = 0; j < 7; j++) {
        #pragma unroll
        for (int off = 16; off; off >>= 1) {
            a_hp[j] += __shfl_xor_sync(0xffffffffu, a_hp[j], off);
            a_pp[j] += __shfl_xor_sync(0xffffffffu, a_pp[j], off);
            a_mp[j] += __shfl_xor_sync(0xffffffffu, a_mp[j], off);
        }
    }
    if (lane == 0) {
        const int tile = byi*GX + bxi;
        #pragma unroll
        for (int j = 0; j < 7; j++) {
            const size_t s = (size_t)batch*NSH + wid*7 + j;
            g_part[(s*3 + 0)*NTILE + tile] = a_hp[j];
            g_part[(s*3 + 1)*NTILE + tile] = a_pp[j];
            g_part[(s*3 + 2)*NTILE + tile] = a_mp[j];
        }
    }

    // ======== per-batch finalizer election ========
    __syncthreads();
    if (tid == 0) {
        __threadfence();
        if (atomicAdd(&g_bctr[batch], 1) == NTILE - 1) {
            s_flag[0] = 1;
            g_bctr[batch] = 0;      // reset for next graph replay
        } else s_flag[0] = 0;
    }
    __syncthreads();
    if (!s_flag[0]) return;

    // ======== mse finalization for this batch (all 224 threads) ========
    const int b = batch;
    __threadfence();   // acquire all writes for batch b

    // phase A: coalesced column sums + edge rows + pred total
    if (tid < 216) {
        {   // g_rsum: c = tid%9, group g = tid/9 (24 groups), rows g+24k
            const int c = tid % 9, g = tid / 9;
            float acc = 0.f;
            const float* base = g_rsum + (size_t)b*H*9;
            for (int y = g; y < H; y += 24) acc += base[y*9 + c];
            sA[g][c] = acc;
        }
        {   // g_eL/g_eR: c = tid%18, group g = tid/18 (12 groups), rows g+12k
            const int c = tid % 18, g = tid / 18;
            float aL = 0.f, aR = 0.f;
            const float* bl = g_eL + (size_t)b*H*18;
            const float* br = g_eR + (size_t)b*H*18;
            for (int y = g; y < H; y += 12) { aL += bl[y*18 + c]; aR += br[y*18 + c]; }
            sL[g][c] = aL; sR[g][c] = aR;
        }
    }
    for (int t = tid; t < 12*45; t += NT) {
        const int r = t / 45, c = t % 45;
        const int y = (r < 6) ? r : (372 + r);
        float v;
        if (c < 9)       v = g_rsum[((size_t)b*H + y)*9 + c];
        else if (c < 27) v = g_eL [((size_t)b*H + y)*18 + (c-9)];
        else             v = g_eR [((size_t)b*H + y)*18 + (c-27)];
        eRaw[r][c] = v;
    }
    if (wid == 6) {
        const float* q = g_ppart + (size_t)b*NTILE;
        float c = q[lane] + q[lane+32] + ((lane < 8) ? q[lane+64] : 0.f);
        #pragma unroll
        for (int off = 16; off; off >>= 1)
            c += __shfl_xor_sync(0xffffffffu, c, off);
        if (lane == 0) ssp = c;
    }
    __syncthreads();

    // phase B: totals
    if (tid < 9)       { float s=0.f; for (int g=0; g<24; g++) s += sA[g][tid];    Tq[tid]   = s; }
    else if (tid < 27) { const int c=tid-9;  float s=0.f; for (int g=0; g<12; g++) s += sL[g][c]; GL[c] = s; }
    else if (tid < 45) { const int c=tid-27; float s=0.f; for (int g=0; g<12; g++) s += sR[g][c]; GR[c] = s; }
    __syncthreads();

    // phase C: window totals and edge-row windows
    if (tid < 21) {
        const int f = tid / 7, j = tid % 7;
        float T = Tq[f] + Tq[3+f] + Tq[6+f];
        for (int k = 0; k < j; k++) T -= GL[f*6 + k];
        for (int k = j; k < 6; k++) T -= GR[f*6 + k];
        ctot[f][j] = T;
    }
    for (int t = tid; t < 252; t += NT) {
        const int r = t / 21, rest = t % 21;
        const int f = rest / 7, j = rest % 7;
        float T = eRaw[r][f] + eRaw[r][3+f] + eRaw[r][6+f];
        for (int k = 0; k < j; k++) T -= eRaw[r][9  + f*6 + k];
        for (int k = j; k < 6; k++) T -= eRaw[r][27 + f*6 + k];
        e_w[r][f][j] = T;
    }
    if (tid >= NSH && tid < 64) s_mse[tid] = 3.4e38f;   // pad 49..63
    __syncthreads();

    // phase D: per-shift mse; warp wid handles shifts wid*7 .. wid*7+6
    {
        #pragma unroll
        for (int q = 0; q < 7; q++) {
            const int s = wid*7 + q;
            float comp[3];
            #pragma unroll
            for (int c = 0; c < 3; c++) {
                const float* base = g_part + (((size_t)b*NSH + s)*3 + c)*NTILE;
                float v = base[lane] + base[lane+32] + ((lane < 8) ? base[lane+64] : 0.f);
                #pragma unroll
                for (int off = 16; off; off >>= 1)
                    v += __shfl_xor_sync(0xffffffffu, v, off);
                comp[c] = v;
            }
            if (lane == 0) {
                const int i = s / 7, jc = s % 7;
                float Sm  = ctot[0][jc];
                float SL  = ctot[1][jc];
                float Shh = ctot[2][jc];
                for (int y = 0; y < i; y++) {
                    Sm -= e_w[y][0][jc]; SL -= e_w[y][1][jc]; Shh -= e_w[y][2][jc];
                }
                for (int t = i + 6; t < 12; t++) {
                    Sm -= e_w[t][0][jc]; SL -= e_w[t][1][jc]; Shh -= e_w[t][2][jc];
                }
                const float hp = comp[0], pp = comp[1], mp = comp[2];
                const float bias = (SL - ssp) / Sm;
                const float num  = Shh - 2.f*hp + pp - 2.f*bias*(SL - mp) + bias*bias*Sm;
                s_mse[s] = num / Sm;
            }
        }
    }
    __syncthreads();

    // phase E: min over shifts -> g_bmin; overall-last -> mean -> out
    #pragma unroll
    for (int off = 32; off; off >>= 1) {
        if (tid < off) s_mse[tid] = fminf(s_mse[tid], s_mse[tid + off]);
        __syncthreads();
    }
    if (tid == 0) {
        g_bmin[b] = s_mse[0];
        __threadfence();
        if (atomicAdd(&g_ctr, 1) == Bn - 1) { s_flag[1] = 1; g_ctr = 0; }
        else s_flag[1] = 0;
    }
    __syncthreads();

    if (s_flag[1]) {
        __threadfence();
        if (tid < 64) s_mse[tid] = g_bmin[tid];
        __syncthreads();
        #pragma unroll
        for (int off = 32; off; off >>= 1) {
            if (tid < off) s_mse[tid] += s_mse[tid + off];
            __syncthreads();
        }
        if (tid == 0) out[0] = s_mse[0] * (1.f / (float)Bn);
    }
}

extern "C" void kernel_launch(void* const* d_in, const int* in_sizes, int n_in,
                              void* d_out, int out_size)
{
    const float* sr = (const float*)d_in[0];
    const float* hr = (const float*)d_in[1];
    const float* mk = (const float*)d_in[2];
    (void)in_sizes; (void)n_in; (void)out_size;

    corr_kernel<<<dim3(GX, GY, Bn), NT>>>(sr, hr, mk, (float*)d_out);
}

// round 12
// speedup vs baseline: 1.0925x; 1.0925x over previous
#include <cuda_runtime.h>

#define Bn 64
#define H  384
#define HH (H*H)
#define BORDER 3
#define CROP 378
#define NSH 49

// corr tiling: 3 x 24 tiles exactly partition 384 x 384 (owned 128 x 16 each)
#define TX 128
#define TY 16
#define GX 3
#define GY 24
#define NTILE (GX*GY)   // 72
#define HALO_W 136      // need 134, pad to 136 (16B-safe rows)
#define HALO_H 22       // TY + 6
#define NT 224          // threads per block (7 warps)

// scratch (static device memory; zero-initialized; no allocations anywhere)
__device__ float g_part [Bn*NSH*3*NTILE];   // corr partials: [b][shift][comp][tile]
__device__ float g_rsum [Bn*H*3*3];         // per (b,y,bx): {Sm,SL,Shh} partial
__device__ float g_eL   [Bn*H*3*6];         // left edge cols 0..5 per field
__device__ float g_eR   [Bn*H*3*6];         // right edge cols 378..383 per field
__device__ float g_ppart[Bn*NTILE];         // per-tile sum of pred
__device__ float g_bmin [Bn];               // per-batch min cMSE
__device__ int   g_bctr [Bn];               // per-batch tile counter (self-resets)
__device__ int   g_ctr;                     // global batch counter (self-resets)

// ---------------------------------------------------------------------------
// corr_kernel: three 7x7 correlations + fused box partials; the LAST block of
// each batch runs mse finalization inline; overall-last reduces to out[0].
// 5 blocks/SM target: no s_pp tile (qv recomputed), regs capped via
// __launch_bounds__(NT, 5).
// ---------------------------------------------------------------------------
__global__ __launch_bounds__(NT, 5) void corr_kernel(
    const float* __restrict__ sr, const float* __restrict__ hr,
    const float* __restrict__ mk, float* __restrict__ out)
{
    __shared__ __align__(16) float s_m [HALO_H*HALO_W];
    __shared__ __align__(16) float s_mh[HALO_H*HALO_W];
    __shared__ __align__(16) float s_p [TY*TX];
    __shared__ float s_red[8];
    // finalizer scratch (cold path, used only after main phase)
    __shared__ float sA[24][9];
    __shared__ float sL[12][18];
    __shared__ float sR[12][18];
    __shared__ float Tq[9], GL[18], GR[18];
    __shared__ float eRaw[12][45];   // [r][0..8 rsum | 9..26 eL | 27..44 eR]
    __shared__ float e_w[12][3][7];
    __shared__ float ctot[3][7];
    __shared__ float ssp;
    __shared__ float s_mse[64];
    __shared__ int   s_flag[2];      // [0]=is_batch_finalizer, [1]=is_last

    const int batch = blockIdx.z;
    const int bxi = blockIdx.x, byi = blockIdx.y;
    const int x0 = bxi * TX;
    const int y0 = byi * TY;
    const float* mb = mk + (size_t)batch*HH;
    const float* hb = hr + (size_t)batch*HH;
    const float* sb = sr + (size_t)batch*HH;
    const int tid  = threadIdx.x;
    const int wid  = tid >> 5;
    const int lane = tid & 31;

    // ---- halo tiles of m and m*h via float4 (rows 22, 34 float4 cols) ----
    for (int idx = tid; idx < HALO_H*34; idx += NT) {
        const int r  = idx / 34, c4 = idx % 34;
        const int y  = y0 + r, x = x0 + c4*4;
        float4 m4 = make_float4(0.f,0.f,0.f,0.f);
        float4 h4 = make_float4(0.f,0.f,0.f,0.f);
        if (y < H && x + 3 < H) {
            m4 = *(const float4*)&mb[y*H + x];
            h4 = *(const float4*)&hb[y*H + x];
            if (c4 == 33) { m4.z = 0.f; m4.w = 0.f; }   // cols 134,135 are pad
        }
        float4 l4;
        l4.x = m4.x*h4.x; l4.y = m4.y*h4.y; l4.z = m4.z*h4.z; l4.w = m4.w*h4.w;
        *(float4*)&s_m [r*HALO_W + c4*4] = m4;
        *(float4*)&s_mh[r*HALO_W + c4*4] = l4;
    }
    __syncthreads();

    // ---- fused box partials from owned 16x128 region ----
    for (int r = wid; r < TY; r += 7) {
        const float4 m4 = *(const float4*)&s_m [r*HALO_W + lane*4];
        const float4 l4 = *(const float4*)&s_mh[r*HALO_W + lane*4];
        float sm = m4.x + m4.y + m4.z + m4.w;
        float sl = l4.x + l4.y + l4.z + l4.w;
        float sh = l4.x*l4.x + l4.y*l4.y + l4.z*l4.z + l4.w*l4.w;  // m*h^2 (m binary)
        #pragma unroll
        for (int off = 16; off; off >>= 1) {
            sm += __shfl_xor_sync(0xffffffffu, sm, off);
            sl += __shfl_xor_sync(0xffffffffu, sl, off);
            sh += __shfl_xor_sync(0xffffffffu, sh, off);
        }
        if (lane == 0) {
            float* q = g_rsum + (((size_t)batch*H + (y0+r))*3 + bxi)*3;
            q[0] = sm; q[1] = sl; q[2] = sh;
        }
    }
    if (bxi == 0 && tid < 96) {
        const int r = tid / 6, c = tid % 6;
        const float m = s_m[r*HALO_W + c], l = s_mh[r*HALO_W + c];
        float* q = g_eL + ((size_t)batch*H + (y0+r))*18;
        q[0*6+c] = m; q[1*6+c] = l; q[2*6+c] = l*l;
    }
    if (bxi == 2 && tid < 96) {
        const int r = tid / 6, c = tid % 6;
        const float m = s_m[r*HALO_W + 122 + c], l = s_mh[r*HALO_W + 122 + c];
        float* q = g_eR + ((size_t)batch*H + (y0+r))*18;
        q[0*6+c] = m; q[1*6+c] = l; q[2*6+c] = l*l;
    }

    // ---- pred tile from sr (global) * mask (smem); accumulate sum(pred) ----
    float tp = 0.f;
    for (int idx = tid; idx < TY*TX; idx += NT) {
        const int r = idx >> 7, c = idx & 127;
        const int y = y0 + r, x = x0 + c;   // pred (crop) coordinates
        float p = 0.f;
        if (y < CROP && x < CROP)
            p = sb[(y+BORDER)*H + (x+BORDER)] * s_m[(r+BORDER)*HALO_W + (c+BORDER)];
        s_p[idx] = p;
        tp += p;
    }
    #pragma unroll
    for (int off = 16; off; off >>= 1)
        tp += __shfl_xor_sync(0xffffffffu, tp, off);
    if (lane == 0) s_red[wid] = tp;
    __syncthreads();
    if (tid == 0) {
        float s = 0.f;
        #pragma unroll
        for (int k = 0; k < 7; k++) s += s_red[k];
        g_ppart[(size_t)batch*NTILE + byi*GX + bxi] = s;
    }

    // ---- main correlation loop (scalar core; qv recomputed from pv) ----
    const int cb = lane * 4;
    float a_hp[7], a_pp[7], a_mp[7];
    #pragma unroll
    for (int j = 0; j < 7; j++) { a_hp[j]=0.f; a_pp[j]=0.f; a_mp[j]=0.f; }

    for (int r = 0; r < TY; r++) {
        const float4 p4 = *(const float4*)&s_p[r*TX + cb];
        const float pv[4] = {p4.x, p4.y, p4.z, p4.w};
        const float qv[4] = {p4.x*p4.x, p4.y*p4.y, p4.z*p4.z, p4.w*p4.w};

        const int hbase = (r + wid)*HALO_W + cb;
        float mw[10], hw[10];
        {
            float4 t; float2 u;
            t = *(const float4*)&s_m[hbase];    mw[0]=t.x; mw[1]=t.y; mw[2]=t.z; mw[3]=t.w;
            t = *(const float4*)&s_m[hbase+4];  mw[4]=t.x; mw[5]=t.y; mw[6]=t.z; mw[7]=t.w;
            u = *(const float2*)&s_m[hbase+8];  mw[8]=u.x; mw[9]=u.y;
            t = *(const float4*)&s_mh[hbase];   hw[0]=t.x; hw[1]=t.y; hw[2]=t.z; hw[3]=t.w;
            t = *(const float4*)&s_mh[hbase+4]; hw[4]=t.x; hw[5]=t.y; hw[6]=t.z; hw[7]=t.w;
            u = *(const float2*)&s_mh[hbase+8]; hw[8]=u.x; hw[9]=u.y;
        }
        #pragma unroll
        for (int j = 0; j < 7; j++) {
            #pragma unroll
            for (int k = 0; k < 4; k++) {
                a_hp[j] = fmaf(hw[j+k], pv[k], a_hp[j]);
                a_mp[j] = fmaf(mw[j+k], pv[k], a_mp[j]);
                a_pp[j] = fmaf(mw[j+k], qv[k], a_pp[j]);
            }
        }
    }

    #pragma unroll
    for (int j = 0; j < 7; j++) {
        #pragma unroll
        for (int off = 16; off; off >>= 1) {
            a_hp[j] += __shfl_xor_sync(0xffffffffu, a_hp[j], off);
            a_pp[j] += __shfl_xor_sync(0xffffffffu, a_pp[j], off);
            a_mp[j] += __shfl_xor_sync(0xffffffffu, a_mp[j], off);
        }
    }
    if (lane == 0) {
        const int tile = byi*GX + bxi;
        #pragma unroll
        for (int j = 0; j < 7; j++) {
            const size_t s = (size_t)batch*NSH + wid*7 + j;
            g_part[(s*3 + 0)*NTILE + tile] = a_hp[j];
            g_part[(s*3 + 1)*NTILE + tile] = a_pp[j];
            g_part[(s*3 + 2)*NTILE + tile] = a_mp[j];
        }
    }

    // ======== per-batch finalizer election ========
    __syncthreads();
    if (tid == 0) {
        __threadfence();
        if (atomicAdd(&g_bctr[batch], 1) == NTILE - 1) {
            s_flag[0] = 1;
            g_bctr[batch] = 0;      // reset for next graph replay
        } else s_flag[0] = 0;
    }
    __syncthreads();
    if (!s_flag[0]) return;

    // ======== mse finalization for this batch (all 224 threads) ========
    const int b = batch;
    __threadfence();   // acquire all writes for batch b

    // phase A: coalesced column sums + edge rows + pred total
    if (tid < 216) {
        {   // g_rsum: c = tid%9, group g = tid/9 (24 groups), rows g+24k
            const int c = tid % 9, g = tid / 9;
            float acc = 0.f;
            const float* base = g_rsum + (size_t)b*H*9;
            for (int y = g; y < H; y += 24) acc += base[y*9 + c];
            sA[g][c] = acc;
        }
        {   // g_eL/g_eR: c = tid%18, group g = tid/18 (12 groups), rows g+12k
            const int c = tid % 18, g = tid / 18;
            float aL = 0.f, aR = 0.f;
            const float* bl = g_eL + (size_t)b*H*18;
            const float* br = g_eR + (size_t)b*H*18;
            for (int y = g; y < H; y += 12) { aL += bl[y*18 + c]; aR += br[y*18 + c]; }
            sL[g][c] = aL; sR[g][c] = aR;
        }
    }
    for (int t = tid; t < 12*45; t += NT) {
        const int r = t / 45, c = t % 45;
        const int y = (r < 6) ? r : (372 + r);
        float v;
        if (c < 9)       v = g_rsum[((size_t)b*H + y)*9 + c];
        else if (c < 27) v = g_eL [((size_t)b*H + y)*18 + (c-9)];
        else             v = g_eR [((size_t)b*H + y)*18 + (c-27)];
        eRaw[r][c] = v;
    }
    if (wid == 6) {
        const float* q = g_ppart + (size_t)b*NTILE;
        float c = q[lane] + q[lane+32] + ((lane < 8) ? q[lane+64] : 0.f);
        #pragma unroll
        for (int off = 16; off; off >>= 1)
            c += __shfl_xor_sync(0xffffffffu, c, off);
        if (lane == 0) ssp = c;
    }
    __syncthreads();

    // phase B: totals
    if (tid < 9)       { float s=0.f; for (int g=0; g<24; g++) s += sA[g][tid];    Tq[tid]   = s; }
    else if (tid < 27) { const int c=tid-9;  float s=0.f; for (int g=0; g<12; g++) s += sL[g][c]; GL[c] = s; }
    else if (tid < 45) { const int c=tid-27; float s=0.f; for (int g=0; g<12; g++) s += sR[g][c]; GR[c] = s; }
    __syncthreads();

    // phase C: window totals and edge-row windows
    if (tid < 21) {
        const int f = tid / 7, j = tid % 7;
        float T = Tq[f] + Tq[3+f] + Tq[6+f];
        for (int k = 0; k < j; k++) T -= GL[f*6 + k];
        for (int k = j; k < 6; k++) T -= GR[f*6 + k];
        ctot[f][j] = T;
    }
    for (int t = tid; t < 252; t += NT) {
        const int r = t / 21, rest = t % 21;
        const int f = rest / 7, j = rest % 7;
        float T = eRaw[r][f] + eRaw[r][3+f] + eRaw[r][6+f];
        for (int k = 0; k < j; k++) T -= eRaw[r][9  + f*6 + k];
        for (int k = j; k < 6; k++) T -= eRaw[r][27 + f*6 + k];
        e_w[r][f][j] = T;
    }
    if (tid >= NSH && tid < 64) s_mse[tid] = 3.4e38f;   // pad 49..63
    __syncthreads();

    // phase D: per-shift mse; warp wid handles shifts wid*7 .. wid*7+6
    {
        #pragma unroll
        for (int q = 0; q < 7; q++) {
            const int s = wid*7 + q;
            float comp[3];
            #pragma unroll
            for (int c = 0; c < 3; c++) {
                const float* base = g_part + (((size_t)b*NSH + s)*3 + c)*NTILE;
                float v = base[lane] + base[lane+32] + ((lane < 8) ? base[lane+64] : 0.f);
                #pragma unroll
                for (int off = 16; off; off >>= 1)
                    v += __shfl_xor_sync(0xffffffffu, v, off);
                comp[c] = v;
            }
            if (lane == 0) {
                const int i = s / 7, jc = s % 7;
                float Sm  = ctot[0][jc];
                float SL  = ctot[1][jc];
                float Shh = ctot[2][jc];
                for (int y = 0; y < i; y++) {
                    Sm -= e_w[y][0][jc]; SL -= e_w[y][1][jc]; Shh -= e_w[y][2][jc];
                }
                for (int t = i + 6; t < 12; t++) {
                    Sm -= e_w[t][0][jc]; SL -= e_w[t][1][jc]; Shh -= e_w[t][2][jc];
                }
                const float hp = comp[0], pp = comp[1], mp = comp[2];
                const float bias = (SL - ssp) / Sm;
                const float num  = Shh - 2.f*hp + pp - 2.f*bias*(SL - mp) + bias*bias*Sm;
                s_mse[s] = num / Sm;
            }
        }
    }
    __syncthreads();

    // phase E: min over shifts -> g_bmin; overall-last -> mean -> out
    #pragma unroll
    for (int off = 32; off; off >>= 1) {
        if (tid < off) s_mse[tid] = fminf(s_mse[tid], s_mse[tid + off]);
        __syncthreads();
    }
    if (tid == 0) {
        g_bmin[b] = s_mse[0];
        __threadfence();
        if (atomicAdd(&g_ctr, 1) == Bn - 1) { s_flag[1] = 1; g_ctr = 0; }
        else s_flag[1] = 0;
    }
    __syncthreads();

    if (s_flag[1]) {
        __threadfence();
        if (tid < 64) s_mse[tid] = g_bmin[tid];
        __syncthreads();
        #pragma unroll
        for (int off = 32; off; off >>= 1) {
            if (tid < off) s_mse[tid] += s_mse[tid + off];
            __syncthreads();
        }
        if (tid == 0) out[0] = s_mse[0] * (1.f / (float)Bn);
    }
}

extern "C" void kernel_launch(void* const* d_in, const int* in_sizes, int n_in,
                              void* d_out, int out_size)
{
    const float* sr = (const float*)d_in[0];
    const float* hr = (const float*)d_in[1];
    const float* mk = (const float*)d_in[2];
    (void)in_sizes; (void)n_in; (void)out_size;

    corr_kernel<<<dim3(GX, GY, Bn), NT>>>(sr, hr, mk, (float*)d_out);
}

// round 13
// speedup vs baseline: 1.2198x; 1.1165x over previous
#include <cuda_runtime.h>

#define Bn 64
#define H  384
#define HH (H*H)
#define BORDER 3
#define CROP 378
#define NSH 49

// corr tiling: 3 x 16 tiles exactly partition 384 x 384 (owned 128 x 24 each)
#define TX 128
#define TY 24
#define GX 3
#define GY 16
#define NTILE (GX*GY)   // 48
#define HALO_W 136      // need 134, pad to 136 (16B-safe rows)
#define HALO_H 30       // TY + 6
#define NT 224          // threads per block (7 warps)

#define MH_ELEMS (HALO_H*HALO_W)          // 4080
#define DYN_FLOATS (2*MH_ELEMS + TY*TX)   // 11232
#define DYN_BYTES (DYN_FLOATS*4)          // 44928

// scratch (static device memory; zero-initialized; no allocations anywhere)
__device__ float g_part [Bn*NSH*3*NTILE];   // corr partials: [b][shift][comp][tile]
__device__ float g_rsum [Bn*H*3*3];         // per (b,y,bx): {Sm,SL,Shh} partial
__device__ float g_eL   [Bn*H*3*6];         // left edge cols 0..5 per field
__device__ float g_eR   [Bn*H*3*6];         // right edge cols 378..383 per field
__device__ float g_ppart[Bn*NTILE];         // per-tile sum of pred
__device__ float g_bmin [Bn];               // per-batch min cMSE
__device__ int   g_bctr [Bn];               // per-batch tile counter (self-resets)
__device__ int   g_ctr;                     // global batch counter (self-resets)

// ---------------------------------------------------------------------------
// corr_kernel: three 7x7 correlations + fused box partials; the LAST block of
// each batch runs mse finalization inline; overall-last reduces to out[0].
// TY=24 tile via dynamic smem (44.9KB) -> 4 blocks/SM, prologue amortized.
// ---------------------------------------------------------------------------
__global__ __launch_bounds__(NT, 4) void corr_kernel(
    const float* __restrict__ sr, const float* __restrict__ hr,
    const float* __restrict__ mk, float* __restrict__ out)
{
    extern __shared__ __align__(16) float dyn[];
    float* s_m  = dyn;                 // [HALO_H][HALO_W]
    float* s_mh = dyn + MH_ELEMS;      // [HALO_H][HALO_W]
    float* s_p  = dyn + 2*MH_ELEMS;    // [TY][TX]

    __shared__ float s_red[8];
    // finalizer scratch (cold path, used only after main phase)
    __shared__ float sA[24][9];
    __shared__ float sL[12][18];
    __shared__ float sR[12][18];
    __shared__ float Tq[9], GL[18], GR[18];
    __shared__ float eRaw[12][45];   // [r][0..8 rsum | 9..26 eL | 27..44 eR]
    __shared__ float e_w[12][3][7];
    __shared__ float ctot[3][7];
    __shared__ float ssp;
    __shared__ float s_mse[64];
    __shared__ int   s_flag[2];      // [0]=is_batch_finalizer, [1]=is_last

    const int batch = blockIdx.z;
    const int bxi = blockIdx.x, byi = blockIdx.y;
    const int x0 = bxi * TX;
    const int y0 = byi * TY;
    const float* mb = mk + (size_t)batch*HH;
    const float* hb = hr + (size_t)batch*HH;
    const float* sb = sr + (size_t)batch*HH;
    const int tid  = threadIdx.x;
    const int wid  = tid >> 5;
    const int lane = tid & 31;

    // ---- phase 0: halo tiles (float4) + raw sr tile, one sync ----
    #pragma unroll
    for (int k = 0; k < 5; k++) {
        const int idx = tid + k*NT;
        if (idx < HALO_H*34) {
            const int r  = idx / 34, c4 = idx % 34;
            const int y  = y0 + r, x = x0 + c4*4;
            float4 m4 = make_float4(0.f,0.f,0.f,0.f);
            float4 h4 = make_float4(0.f,0.f,0.f,0.f);
            if (y < H && x + 3 < H) {
                m4 = *(const float4*)&mb[y*H + x];
                h4 = *(const float4*)&hb[y*H + x];
                if (c4 == 33) { m4.z = 0.f; m4.w = 0.f; }   // cols 134,135 pad
            }
            float4 l4;
            l4.x = m4.x*h4.x; l4.y = m4.y*h4.y; l4.z = m4.z*h4.z; l4.w = m4.w*h4.w;
            *(float4*)&s_m [r*HALO_W + c4*4] = m4;
            *(float4*)&s_mh[r*HALO_W + c4*4] = l4;
        }
    }
    #pragma unroll
    for (int k = 0; k < 14; k++) {
        const int idx = tid + k*NT;
        if (idx < TY*TX) {
            const int r = idx >> 7, c = idx & 127;
            const int y = y0 + r, x = x0 + c;
            float v = 0.f;
            if (y < CROP && x < CROP)
                v = sb[(y+BORDER)*H + (x+BORDER)];
            s_p[idx] = v;
        }
    }
    __syncthreads();

    // ---- fused box partials from owned 24x128 region ----
    for (int r = wid; r < TY; r += 7) {
        const float4 m4 = *(const float4*)&s_m [r*HALO_W + lane*4];
        const float4 l4 = *(const float4*)&s_mh[r*HALO_W + lane*4];
        float sm = m4.x + m4.y + m4.z + m4.w;
        float sl = l4.x + l4.y + l4.z + l4.w;
        float sh = l4.x*l4.x + l4.y*l4.y + l4.z*l4.z + l4.w*l4.w;  // m*h^2 (m binary)
        #pragma unroll
        for (int off = 16; off; off >>= 1) {
            sm += __shfl_xor_sync(0xffffffffu, sm, off);
            sl += __shfl_xor_sync(0xffffffffu, sl, off);
            sh += __shfl_xor_sync(0xffffffffu, sh, off);
        }
        if (lane == 0) {
            float* q = g_rsum + (((size_t)batch*H + (y0+r))*3 + bxi)*3;
            q[0] = sm; q[1] = sl; q[2] = sh;
        }
    }
    if (bxi == 0 && tid < TY*6) {
        const int r = tid / 6, c = tid % 6;
        const float m = s_m[r*HALO_W + c], l = s_mh[r*HALO_W + c];
        float* q = g_eL + ((size_t)batch*H + (y0+r))*18;
        q[0*6+c] = m; q[1*6+c] = l; q[2*6+c] = l*l;
    }
    if (bxi == 2 && tid < TY*6) {
        const int r = tid / 6, c = tid % 6;
        const float m = s_m[r*HALO_W + 122 + c], l = s_mh[r*HALO_W + 122 + c];
        float* q = g_eR + ((size_t)batch*H + (y0+r))*18;
        q[0*6+c] = m; q[1*6+c] = l; q[2*6+c] = l*l;
    }

    // ---- mask-multiply pred tile in place; accumulate sum(pred) ----
    float tp = 0.f;
    #pragma unroll
    for (int k = 0; k < 14; k++) {
        const int idx = tid + k*NT;
        if (idx < TY*TX) {
            const int r = idx >> 7, c = idx & 127;
            const float p = s_p[idx] * s_m[(r+BORDER)*HALO_W + (c+BORDER)];
            s_p[idx] = p;
            tp += p;
        }
    }
    #pragma unroll
    for (int off = 16; off; off >>= 1)
        tp += __shfl_xor_sync(0xffffffffu, tp, off);
    if (lane == 0) s_red[wid] = tp;
    __syncthreads();
    if (tid == 0) {
        float s = 0.f;
        #pragma unroll
        for (int k = 0; k < 7; k++) s += s_red[k];
        g_ppart[(size_t)batch*NTILE + byi*GX + bxi] = s;
    }

    // ---- main correlation loop (scalar core; qv recomputed from pv) ----
    const int cb = lane * 4;
    float a_hp[7], a_pp[7], a_mp[7];
    #pragma unroll
    for (int j = 0; j < 7; j++) { a_hp[j]=0.f; a_pp[j]=0.f; a_mp[j]=0.f; }

    for (int r = 0; r < TY; r++) {
        const float4 p4 = *(const float4*)&s_p[r*TX + cb];
        const float pv[4] = {p4.x, p4.y, p4.z, p4.w};
        const float qv[4] = {p4.x*p4.x, p4.y*p4.y, p4.z*p4.z, p4.w*p4.w};

        const int hbase = (r + wid)*HALO_W + cb;
        float mw[10], hw[10];
        {
            float4 t; float2 u;
            t = *(const float4*)&s_m[hbase];    mw[0]=t.x; mw[1]=t.y; mw[2]=t.z; mw[3]=t.w;
            t = *(const float4*)&s_m[hbase+4];  mw[4]=t.x; mw[5]=t.y; mw[6]=t.z; mw[7]=t.w;
            u = *(const float2*)&s_m[hbase+8];  mw[8]=u.x; mw[9]=u.y;
            t = *(const float4*)&s_mh[hbase];   hw[0]=t.x; hw[1]=t.y; hw[2]=t.z; hw[3]=t.w;
            t = *(const float4*)&s_mh[hbase+4]; hw[4]=t.x; hw[5]=t.y; hw[6]=t.z; hw[7]=t.w;
            u = *(const float2*)&s_mh[hbase+8]; hw[8]=u.x; hw[9]=u.y;
        }
        #pragma unroll
        for (int j = 0; j < 7; j++) {
            #pragma unroll
            for (int k = 0; k < 4; k++) {
                a_hp[j] = fmaf(hw[j+k], pv[k], a_hp[j]);
                a_mp[j] = fmaf(mw[j+k], pv[k], a_mp[j]);
                a_pp[j] = fmaf(mw[j+k], qv[k], a_pp[j]);
            }
        }
    }

    #pragma unroll
    for (int j = 0; j < 7; j++) {
        #pragma unroll
        for (int off = 16; off; off >>= 1) {
            a_hp[j] += __shfl_xor_sync(0xffffffffu, a_hp[j], off);
            a_pp[j] += __shfl_xor_sync(0xffffffffu, a_pp[j], off);
            a_mp[j] += __shfl_xor_sync(0xffffffffu, a_mp[j], off);
        }
    }
    if (lane == 0) {
        const int tile = byi*GX + bxi;
        #pragma unroll
        for (int j = 0; j < 7; j++) {
            const size_t s = (size_t)batch*NSH + wid*7 + j;
            g_part[(s*3 + 0)*NTILE + tile] = a_hp[j];
            g_part[(s*3 + 1)*NTILE + tile] = a_pp[j];
            g_part[(s*3 + 2)*NTILE + tile] = a_mp[j];
        }
    }

    // ======== per-batch finalizer election ========
    __syncthreads();
    if (tid == 0) {
        __threadfence();
        if (atomicAdd(&g_bctr[batch], 1) == NTILE - 1) {
            s_flag[0] = 1;
            g_bctr[batch] = 0;      // reset for next graph replay
        } else s_flag[0] = 0;
    }
    __syncthreads();
    if (!s_flag[0]) return;

    // ======== mse finalization for this batch (all 224 threads) ========
    const int b = batch;
    __threadfence();   // acquire all writes for batch b

    // phase A: coalesced column sums + edge rows + pred total
    if (tid < 216) {
        {   // g_rsum: c = tid%9, group g = tid/9 (24 groups), rows g+24k
            const int c = tid % 9, g = tid / 9;
            float acc = 0.f;
            const float* base = g_rsum + (size_t)b*H*9;
            for (int y = g; y < H; y += 24) acc += base[y*9 + c];
            sA[g][c] = acc;
        }
        {   // g_eL/g_eR: c = tid%18, group g = tid/18 (12 groups), rows g+12k
            const int c = tid % 18, g = tid / 18;
            float aL = 0.f, aR = 0.f;
            const float* bl = g_eL + (size_t)b*H*18;
            const float* br = g_eR + (size_t)b*H*18;
            for (int y = g; y < H; y += 12) { aL += bl[y*18 + c]; aR += br[y*18 + c]; }
            sL[g][c] = aL; sR[g][c] = aR;
        }
    }
    for (int t = tid; t < 12*45; t += NT) {
        const int r = t / 45, c = t % 45;
        const int y = (r < 6) ? r : (372 + r);
        float v;
        if (c < 9)       v = g_rsum[((size_t)b*H + y)*9 + c];
        else if (c < 27) v = g_eL [((size_t)b*H + y)*18 + (c-9)];
        else             v = g_eR [((size_t)b*H + y)*18 + (c-27)];
        eRaw[r][c] = v;
    }
    if (wid == 6) {
        const float* q = g_ppart + (size_t)b*NTILE;
        float c = q[lane] + ((lane < NTILE-32) ? q[lane+32] : 0.f);
        #pragma unroll
        for (int off = 16; off; off >>= 1)
            c += __shfl_xor_sync(0xffffffffu, c, off);
        if (lane == 0) ssp = c;
    }
    __syncthreads();

    // phase B: totals
    if (tid < 9)       { float s=0.f; for (int g=0; g<24; g++) s += sA[g][tid];    Tq[tid]   = s; }
    else if (tid < 27) { const int c=tid-9;  float s=0.f; for (int g=0; g<12; g++) s += sL[g][c]; GL[c] = s; }
    else if (tid < 45) { const int c=tid-27; float s=0.f; for (int g=0; g<12; g++) s += sR[g][c]; GR[c] = s; }
    __syncthreads();

    // phase C: window totals and edge-row windows
    if (tid < 21) {
        const int f = tid / 7, j = tid % 7;
        float T = Tq[f] + Tq[3+f] + Tq[6+f];
        for (int k = 0; k < j; k++) T -= GL[f*6 + k];
        for (int k = j; k < 6; k++) T -= GR[f*6 + k];
        ctot[f][j] = T;
    }
    for (int t = tid; t < 252; t += NT) {
        const int r = t / 21, rest = t % 21;
        const int f = rest / 7, j = rest % 7;
        float T = eRaw[r][f] + eRaw[r][3+f] + eRaw[r][6+f];
        for (int k = 0; k < j; k++) T -= eRaw[r][9  + f*6 + k];
        for (int k = j; k < 6; k++) T -= eRaw[r][27 + f*6 + k];
        e_w[r][f][j] = T;
    }
    if (tid >= NSH && tid < 64) s_mse[tid] = 3.4e38f;   // pad 49..63
    __syncthreads();

    // phase D: per-shift mse; warp wid handles shifts wid*7 .. wid*7+6
    {
        #pragma unroll
        for (int q = 0; q < 7; q++) {
            const int s = wid*7 + q;
            float comp[3];
            #pragma unroll
            for (int c = 0; c < 3; c++) {
                const float* base = g_part + (((size_t)b*NSH + s)*3 + c)*NTILE;
                float v = base[lane] + ((lane < NTILE-32) ? base[lane+32] : 0.f);
                #pragma unroll
                for (int off = 16; off; off >>= 1)
                    v += __shfl_xor_sync(0xffffffffu, v, off);
                comp[c] = v;
            }
            if (lane == 0) {
                const int i = s / 7, jc = s % 7;
                float Sm  = ctot[0][jc];
                float SL  = ctot[1][jc];
                float Shh = ctot[2][jc];
                for (int y = 0; y < i; y++) {
                    Sm -= e_w[y][0][jc]; SL -= e_w[y][1][jc]; Shh -= e_w[y][2][jc];
                }
                for (int t = i + 6; t < 12; t++) {
                    Sm -= e_w[t][0][jc]; SL -= e_w[t][1][jc]; Shh -= e_w[t][2][jc];
                }
                const float hp = comp[0], pp = comp[1], mp = comp[2];
                const float bias = (SL - ssp) / Sm;
                const float num  = Shh - 2.f*hp + pp - 2.f*bias*(SL - mp) + bias*bias*Sm;
                s_mse[s] = num / Sm;
            }
        }
    }
    __syncthreads();

    // phase E: min over shifts -> g_bmin; overall-last -> mean -> out
    #pragma unroll
    for (int off = 32; off; off >>= 1) {
        if (tid < off) s_mse[tid] = fminf(s_mse[tid], s_mse[tid + off]);
        __syncthreads();
    }
    if (tid == 0) {
        g_bmin[b] = s_mse[0];
        __threadfence();
        if (atomicAdd(&g_ctr, 1) == Bn - 1) { s_flag[1] = 1; g_ctr = 0; }
        else s_flag[1] = 0;
    }
    __syncthreads();

    if (s_flag[1]) {
        __threadfence();
        if (tid < 64) s_mse[tid] = g_bmin[tid];
        __syncthreads();
        #pragma unroll
        for (int off = 32; off; off >>= 1) {
            if (tid < off) s_mse[tid] += s_mse[tid + off];
            __syncthreads();
        }
        if (tid == 0) out[0] = s_mse[0] * (1.f / (float)Bn);
    }
}

extern "C" void kernel_launch(void* const* d_in, const int* in_sizes, int n_in,
                              void* d_out, int out_size)
{
    const float* sr = (const float*)d_in[0];
    const float* hr = (const float*)d_in[1];
    const float* mk = (const float*)d_in[2];
    (void)in_sizes; (void)n_in; (void)out_size;

    cudaFuncSetAttribute(corr_kernel,
                         cudaFuncAttributeMaxDynamicSharedMemorySize, DYN_BYTES);
    corr_kernel<<<dim3(GX, GY, Bn), NT, DYN_BYTES>>>(sr, hr, mk, (float*)d_out);
}

// round 14
// speedup vs baseline: 1.2615x; 1.0342x over previous
#include <cuda_runtime.h>

#define Bn 64
#define H  384
#define HH (H*H)
#define BORDER 3
#define CROP 378
#define NSH 49

// corr tiling: 3 x 16 tiles exactly partition 384 x 384 (owned 128 x 24 each)
#define TX 128
#define TY 24
#define GX 3
#define GY 16
#define NTILE (GX*GY)   // 48
#define HALO_W 136      // need 134, pad to 136 (16B-safe rows)
#define HALO_H 30       // TY + 6
#define NT 224          // threads per block (7 warps)

#define MH_ELEMS (HALO_H*HALO_W)          // 4080
#define DYN_FLOATS (2*MH_ELEMS + TY*TX)   // 11232
#define DYN_BYTES (DYN_FLOATS*4)          // 44928

// scratch (static device memory; zero-initialized; no allocations anywhere)
__device__ float g_part [Bn*NSH*3*NTILE];   // corr partials: [b][shift][comp][tile]
__device__ float g_rsum [Bn*H*3*3];         // per (b,y,bx): {Sm,SL,Shh} partial
__device__ float g_eL   [Bn*H*3*6];         // left edge cols 0..5 per field
__device__ float g_eR   [Bn*H*3*6];         // right edge cols 378..383 per field
__device__ float g_ppart[Bn*NTILE];         // per-tile sum of pred
__device__ float g_bmin [Bn];               // per-batch min cMSE
__device__ int   g_bctr [Bn];               // per-batch tile counter (self-resets)
__device__ int   g_ctr;                     // global batch counter (self-resets)

// ---------------------------------------------------------------------------
// corr_kernel: three 7x7 correlations + fused box partials; the LAST block of
// each batch runs mse finalization inline; overall-last reduces to out[0].
// TY=24 tile via dynamic smem; finalizer scratch OVERLAID on the dynamic
// region (dead after mainloop) -> ~45KB/block -> 5 blocks/SM, reg cap 56.
// ---------------------------------------------------------------------------
__global__ __launch_bounds__(NT, 5) void corr_kernel(
    const float* __restrict__ sr, const float* __restrict__ hr,
    const float* __restrict__ mk, float* __restrict__ out)
{
    extern __shared__ __align__(16) float dyn[];
    float* s_m  = dyn;                 // [HALO_H][HALO_W]
    float* s_mh = dyn + MH_ELEMS;      // [HALO_H][HALO_W]
    float* s_p  = dyn + 2*MH_ELEMS;    // [TY][TX]

    __shared__ float s_red[8];
    __shared__ int   s_flag[2];      // [0]=is_batch_finalizer, [1]=is_last

    const int batch = blockIdx.z;
    const int bxi = blockIdx.x, byi = blockIdx.y;
    const int x0 = bxi * TX;
    const int y0 = byi * TY;
    const float* mb = mk + (size_t)batch*HH;
    const float* hb = hr + (size_t)batch*HH;
    const float* sb = sr + (size_t)batch*HH;
    const int tid  = threadIdx.x;
    const int wid  = tid >> 5;
    const int lane = tid & 31;

    // ---- phase 0: halo tiles (float4) + raw sr tile, one sync ----
    #pragma unroll
    for (int k = 0; k < 5; k++) {
        const int idx = tid + k*NT;
        if (idx < HALO_H*34) {
            const int r  = idx / 34, c4 = idx % 34;
            const int y  = y0 + r, x = x0 + c4*4;
            float4 m4 = make_float4(0.f,0.f,0.f,0.f);
            float4 h4 = make_float4(0.f,0.f,0.f,0.f);
            if (y < H && x + 3 < H) {
                m4 = *(const float4*)&mb[y*H + x];
                h4 = *(const float4*)&hb[y*H + x];
                if (c4 == 33) { m4.z = 0.f; m4.w = 0.f; }   // cols 134,135 pad
            }
            float4 l4;
            l4.x = m4.x*h4.x; l4.y = m4.y*h4.y; l4.z = m4.z*h4.z; l4.w = m4.w*h4.w;
            *(float4*)&s_m [r*HALO_W + c4*4] = m4;
            *(float4*)&s_mh[r*HALO_W + c4*4] = l4;
        }
    }
    #pragma unroll
    for (int k = 0; k < 14; k++) {
        const int idx = tid + k*NT;
        if (idx < TY*TX) {
            const int r = idx >> 7, c = idx & 127;
            const int y = y0 + r, x = x0 + c;
            float v = 0.f;
            if (y < CROP && x < CROP)
                v = sb[(y+BORDER)*H + (x+BORDER)];
            s_p[idx] = v;
        }
    }
    __syncthreads();

    // ---- fused box partials from owned 24x128 region ----
    for (int r = wid; r < TY; r += 7) {
        const float4 m4 = *(const float4*)&s_m [r*HALO_W + lane*4];
        const float4 l4 = *(const float4*)&s_mh[r*HALO_W + lane*4];
        float sm = m4.x + m4.y + m4.z + m4.w;
        float sl = l4.x + l4.y + l4.z + l4.w;
        float sh = l4.x*l4.x + l4.y*l4.y + l4.z*l4.z + l4.w*l4.w;  // m*h^2 (m binary)
        #pragma unroll
        for (int off = 16; off; off >>= 1) {
            sm += __shfl_xor_sync(0xffffffffu, sm, off);
            sl += __shfl_xor_sync(0xffffffffu, sl, off);
            sh += __shfl_xor_sync(0xffffffffu, sh, off);
        }
        if (lane == 0) {
            float* q = g_rsum + (((size_t)batch*H + (y0+r))*3 + bxi)*3;
            q[0] = sm; q[1] = sl; q[2] = sh;
        }
    }
    if (bxi == 0 && tid < TY*6) {
        const int r = tid / 6, c = tid % 6;
        const float m = s_m[r*HALO_W + c], l = s_mh[r*HALO_W + c];
        float* q = g_eL + ((size_t)batch*H + (y0+r))*18;
        q[0*6+c] = m; q[1*6+c] = l; q[2*6+c] = l*l;
    }
    if (bxi == 2 && tid < TY*6) {
        const int r = tid / 6, c = tid % 6;
        const float m = s_m[r*HALO_W + 122 + c], l = s_mh[r*HALO_W + 122 + c];
        float* q = g_eR + ((size_t)batch*H + (y0+r))*18;
        q[0*6+c] = m; q[1*6+c] = l; q[2*6+c] = l*l;
    }

    // ---- mask-multiply pred tile in place; accumulate sum(pred) ----
    float tp = 0.f;
    #pragma unroll
    for (int k = 0; k < 14; k++) {
        const int idx = tid + k*NT;
        if (idx < TY*TX) {
            const int r = idx >> 7, c = idx & 127;
            const float p = s_p[idx] * s_m[(r+BORDER)*HALO_W + (c+BORDER)];
            s_p[idx] = p;
            tp += p;
        }
    }
    #pragma unroll
    for (int off = 16; off; off >>= 1)
        tp += __shfl_xor_sync(0xffffffffu, tp, off);
    if (lane == 0) s_red[wid] = tp;
    __syncthreads();
    if (tid == 0) {
        float s = 0.f;
        #pragma unroll
        for (int k = 0; k < 7; k++) s += s_red[k];
        g_ppart[(size_t)batch*NTILE + byi*GX + bxi] = s;
    }

    // ---- main correlation loop (scalar core; qv recomputed from pv) ----
    const int cb = lane * 4;
    float a_hp[7], a_pp[7], a_mp[7];
    #pragma unroll
    for (int j = 0; j < 7; j++) { a_hp[j]=0.f; a_pp[j]=0.f; a_mp[j]=0.f; }

    for (int r = 0; r < TY; r++) {
        const float4 p4 = *(const float4*)&s_p[r*TX + cb];
        const float pv[4] = {p4.x, p4.y, p4.z, p4.w};
        const float qv[4] = {p4.x*p4.x, p4.y*p4.y, p4.z*p4.z, p4.w*p4.w};

        const int hbase = (r + wid)*HALO_W + cb;
        float mw[10], hw[10];
        {
            float4 t; float2 u;
            t = *(const float4*)&s_m[hbase];    mw[0]=t.x; mw[1]=t.y; mw[2]=t.z; mw[3]=t.w;
            t = *(const float4*)&s_m[hbase+4];  mw[4]=t.x; mw[5]=t.y; mw[6]=t.z; mw[7]=t.w;
            u = *(const float2*)&s_m[hbase+8];  mw[8]=u.x; mw[9]=u.y;
            t = *(const float4*)&s_mh[hbase];   hw[0]=t.x; hw[1]=t.y; hw[2]=t.z; hw[3]=t.w;
            t = *(const float4*)&s_mh[hbase+4]; hw[4]=t.x; hw[5]=t.y; hw[6]=t.z; hw[7]=t.w;
            u = *(const float2*)&s_mh[hbase+8]; hw[8]=u.x; hw[9]=u.y;
        }
        #pragma unroll
        for (int j = 0; j < 7; j++) {
            #pragma unroll
            for (int k = 0; k < 4; k++) {
                a_hp[j] = fmaf(hw[j+k], pv[k], a_hp[j]);
                a_mp[j] = fmaf(mw[j+k], pv[k], a_mp[j]);
                a_pp[j] = fmaf(mw[j+k], qv[k], a_pp[j]);
            }
        }
    }

    #pragma unroll
    for (int j = 0; j < 7; j++) {
        #pragma unroll
        for (int off = 16; off; off >>= 1) {
            a_hp[j] += __shfl_xor_sync(0xffffffffu, a_hp[j], off);
            a_pp[j] += __shfl_xor_sync(0xffffffffu, a_pp[j], off);
            a_mp[j] += __shfl_xor_sync(0xffffffffu, a_mp[j], off);
        }
    }
    if (lane == 0) {
        const int tile = byi*GX + bxi;
        #pragma unroll
        for (int j = 0; j < 7; j++) {
            const size_t s = (size_t)batch*NSH + wid*7 + j;
            g_part[(s*3 + 0)*NTILE + tile] = a_hp[j];
            g_part[(s*3 + 1)*NTILE + tile] = a_pp[j];
            g_part[(s*3 + 2)*NTILE + tile] = a_mp[j];
        }
    }

    // ======== per-batch finalizer election ========
    __syncthreads();
    if (tid == 0) {
        __threadfence();
        if (atomicAdd(&g_bctr[batch], 1) == NTILE - 1) {
            s_flag[0] = 1;
            g_bctr[batch] = 0;      // reset for next graph replay
        } else s_flag[0] = 0;
    }
    __syncthreads();
    if (!s_flag[0]) return;

    // ======== mse finalization for this batch (all 224 threads) ========
    // Scratch OVERLAID on dynamic smem (s_m/s_mh/s_p are dead past here;
    // the elections's __syncthreads() ordered all prior smem reads).
    float (*sA)[9]     = (float(*)[9])   (dyn);           // 24 x 9
    float (*sL)[18]    = (float(*)[18])  (dyn + 216);     // 12 x 18
    float (*sR)[18]    = (float(*)[18])  (dyn + 432);     // 12 x 18
    float  *Tq         =                  dyn + 648;      // 9
    float  *GL         =                  dyn + 657;      // 18
    float  *GR         =                  dyn + 675;      // 18
    float (*eRaw)[45]  = (float(*)[45])  (dyn + 693);     // 12 x 45
    float (*e_w)[3][7] = (float(*)[3][7])(dyn + 1233);    // 12 x 3 x 7
    float (*ctot)[7]   = (float(*)[7])   (dyn + 1485);    // 3 x 7
    float  *ssp        =                  dyn + 1506;     // 1
    float  *s_mse      =                  dyn + 1507;     // 64

    const int b = batch;
    __threadfence();   // acquire all writes for batch b

    // phase A: coalesced column sums + edge rows + pred total
    if (tid < 216) {
        {   // g_rsum: c = tid%9, group g = tid/9 (24 groups), rows g+24k
            const int c = tid % 9, g = tid / 9;
            float acc = 0.f;
            const float* base = g_rsum + (size_t)b*H*9;
            for (int y = g; y < H; y += 24) acc += base[y*9 + c];
            sA[g][c] = acc;
        }
        {   // g_eL/g_eR: c = tid%18, group g = tid/18 (12 groups), rows g+12k
            const int c = tid % 18, g = tid / 18;
            float aL = 0.f, aR = 0.f;
            const float* bl = g_eL + (size_t)b*H*18;
            const float* br = g_eR + (size_t)b*H*18;
            for (int y = g; y < H; y += 12) { aL += bl[y*18 + c]; aR += br[y*18 + c]; }
            sL[g][c] = aL; sR[g][c] = aR;
        }
    }
    for (int t = tid; t < 12*45; t += NT) {
        const int r = t / 45, c = t % 45;
        const int y = (r < 6) ? r : (372 + r);
        float v;
        if (c < 9)       v = g_rsum[((size_t)b*H + y)*9 + c];
        else if (c < 27) v = g_eL [((size_t)b*H + y)*18 + (c-9)];
        else             v = g_eR [((size_t)b*H + y)*18 + (c-27)];
        eRaw[r][c] = v;
    }
    if (wid == 6) {
        const float* q = g_ppart + (size_t)b*NTILE;
        float c = q[lane] + ((lane < NTILE-32) ? q[lane+32] : 0.f);
        #pragma unroll
        for (int off = 16; off; off >>= 1)
            c += __shfl_xor_sync(0xffffffffu, c, off);
        if (lane == 0) *ssp = c;
    }
    __syncthreads();

    // phase B: totals
    if (tid < 9)       { float s=0.f; for (int g=0; g<24; g++) s += sA[g][tid];    Tq[tid]   = s; }
    else if (tid < 27) { const int c=tid-9;  float s=0.f; for (int g=0; g<12; g++) s += sL[g][c]; GL[c] = s; }
    else if (tid < 45) { const int c=tid-27; float s=0.f; for (int g=0; g<12; g++) s += sR[g][c]; GR[c] = s; }
    __syncthreads();

    // phase C: window totals and edge-row windows
    if (tid < 21) {
        const int f = tid / 7, j = tid % 7;
        float T = Tq[f] + Tq[3+f] + Tq[6+f];
        for (int k = 0; k < j; k++) T -= GL[f*6 + k];
        for (int k = j; k < 6; k++) T -= GR[f*6 + k];
        ctot[f][j] = T;
    }
    for (int t = tid; t < 252; t += NT) {
        const int r = t / 21, rest = t % 21;
        const int f = rest / 7, j = rest % 7;
        float T = eRaw[r][f] + eRaw[r][3+f] + eRaw[r][6+f];
        for (int k = 0; k < j; k++) T -= eRaw[r][9  + f*6 + k];
        for (int k = j; k < 6; k++) T -= eRaw[r][27 + f*6 + k];
        e_w[r][f][j] = T;
    }
    if (tid >= NSH && tid < 64) s_mse[tid] = 3.4e38f;   // pad 49..63
    __syncthreads();

    // phase D: per-shift mse; warp wid handles shifts wid*7 .. wid*7+6
    {
        #pragma unroll
        for (int q = 0; q < 7; q++) {
            const int s = wid*7 + q;
            float comp[3];
            #pragma unroll
            for (int c = 0; c < 3; c++) {
                const float* base = g_part + (((size_t)b*NSH + s)*3 + c)*NTILE;
                float v = base[lane] + ((lane < NTILE-32) ? base[lane+32] : 0.f);
                #pragma unroll
                for (int off = 16; off; off >>= 1)
                    v += __shfl_xor_sync(0xffffffffu, v, off);
                comp[c] = v;
            }
            if (lane == 0) {
                const int i = s / 7, jc = s % 7;
                float Sm  = ctot[0][jc];
                float SL  = ctot[1][jc];
                float Shh = ctot[2][jc];
                for (int y = 0; y < i; y++) {
                    Sm -= e_w[y][0][jc]; SL -= e_w[y][1][jc]; Shh -= e_w[y][2][jc];
                }
                for (int t = i + 6; t < 12; t++) {
                    Sm -= e_w[t][0][jc]; SL -= e_w[t][1][jc]; Shh -= e_w[t][2][jc];
                }
                const float hp = comp[0], pp = comp[1], mp = comp[2];
                const float bias = (SL - *ssp) / Sm;
                const float num  = Shh - 2.f*hp + pp - 2.f*bias*(SL - mp) + bias*bias*Sm;
                s_mse[s] = num / Sm;
            }
        }
    }
    __syncthreads();

    // phase E: min over shifts -> g_bmin; overall-last -> mean -> out
    #pragma unroll
    for (int off = 32; off; off >>= 1) {
        if (tid < off) s_mse[tid] = fminf(s_mse[tid], s_mse[tid + off]);
        __syncthreads();
    }
    if (tid == 0) {
        g_bmin[b] = s_mse[0];
        __threadfence();
        if (atomicAdd(&g_ctr, 1) == Bn - 1) { s_flag[1] = 1; g_ctr = 0; }
        else s_flag[1] = 0;
    }
    __syncthreads();

    if (s_flag[1]) {
        __threadfence();
        if (tid < 64) s_mse[tid] = g_bmin[tid];
        __syncthreads();
        #pragma unroll
        for (int off = 32; off; off >>= 1) {
            if (tid < off) s_mse[tid] += s_mse[tid + off];
            __syncthreads();
        }
        if (tid == 0) out[0] = s_mse[0] * (1.f / (float)Bn);
    }
}

extern "C" void kernel_launch(void* const* d_in, const int* in_sizes, int n_in,
                              void* d_out, int out_size)
{
    const float* sr = (const float*)d_in[0];
    const float* hr = (const float*)d_in[1];
    const float* mk = (const float*)d_in[2];
    (void)in_sizes; (void)n_in; (void)out_size;

    cudaFuncSetAttribute(corr_kernel,
                         cudaFuncAttributeMaxDynamicSharedMemorySize, DYN_BYTES);
    corr_kernel<<<dim3(GX, GY, Bn), NT, DYN_BYTES>>>(sr, hr, mk, (float*)d_out);
}

// round 15
// speedup vs baseline: 1.4110x; 1.1185x over previous
#include <cuda_runtime.h>

#define Bn 64
#define H  384
#define HH (H*H)
#define BORDER 3
#define CROP 378
#define NSH 49

// corr tiling: 3 x 16 tiles exactly partition 384 x 384 (owned 128 x 24 each)
#define TX 128
#define TY 24
#define GX 3
#define GY 16
#define NTILE (GX*GY)   // 48
#define HALO_W 136      // need 134, pad to 136
#define HALO_H 30       // TY + 6
#define NT 256          // 8 warps

#define MH_ELEMS (HALO_H*HALO_W)          // 4080
#define SP_STRIDE 132                     // bank-spread: 4*pr+col covers 32 banks
#define SP_ELEMS (TY*SP_STRIDE)           // 3168
#define DYN_FLOATS (2*MH_ELEMS + SP_ELEMS) // 11328
#define DYN_BYTES (DYN_FLOATS*4)          // 45312

typedef unsigned int uint32;

// scratch (static device memory; zero-initialized; no allocations anywhere)
__device__ float g_part [Bn*NSH*3*NTILE];   // corr partials: [b][shift][comp][tile]
__device__ float g_rsum [Bn*H*3*3];         // per (b,y,bx): {Sm,SL,Shh} partial
__device__ float g_eL   [Bn*H*3*6];         // left edge cols 0..5 per field
__device__ float g_eR   [Bn*H*3*6];         // right edge cols 378..383 per field
__device__ float g_ppart[Bn*NTILE];         // per-tile sum of pred
__device__ float g_bmin [Bn];               // per-batch min cMSE
__device__ int   g_bctr [Bn];               // per-batch tile counter (self-resets)
__device__ int   g_ctr;                     // global batch counter (self-resets)

__device__ __forceinline__ uint32 f2tf32(float x) {
    uint32 r; asm("cvt.rna.tf32.f32 %0, %1;" : "=r"(r) : "f"(x)); return r;
}
__device__ __forceinline__ void mma_tf32(float c[4], uint32 a0, uint32 a1,
                                         uint32 a2, uint32 a3, uint32 b0, uint32 b1) {
    asm volatile("mma.sync.aligned.m16n8k8.row.col.f32.tf32.tf32.f32 "
        "{%0,%1,%2,%3}, {%4,%5,%6,%7}, {%8,%9}, {%0,%1,%2,%3};"
        : "+f"(c[0]), "+f"(c[1]), "+f"(c[2]), "+f"(c[3])
        : "r"(a0), "r"(a1), "r"(a2), "r"(a3), "r"(b0), "r"(b1));
}

// ---------------------------------------------------------------------------
// corr_kernel: 7x7 correlations via tf32 tensor MMA + fused box partials;
// last block per batch runs mse finalization; overall-last writes out[0].
// ---------------------------------------------------------------------------
__global__ __launch_bounds__(NT, 4) void corr_kernel(
    const float* __restrict__ sr, const float* __restrict__ hr,
    const float* __restrict__ mk, float* __restrict__ out)
{
    extern __shared__ __align__(16) float dyn[];
    float* s_m  = dyn;                 // [HALO_H][HALO_W]
    float* s_mh = dyn + MH_ELEMS;      // [HALO_H][HALO_W] (tf32-rounded)
    float* s_p  = dyn + 2*MH_ELEMS;    // [TY][SP_STRIDE]  (tf32-rounded pred)

    __shared__ float s_red[8];
    __shared__ int   s_flag[2];

    const int batch = blockIdx.z;
    const int bxi = blockIdx.x, byi = blockIdx.y;
    const int x0 = bxi * TX;
    const int y0 = byi * TY;
    const float* mb = mk + (size_t)batch*HH;
    const float* hb = hr + (size_t)batch*HH;
    const float* sb = sr + (size_t)batch*HH;
    const int tid  = threadIdx.x;
    const int wid  = tid >> 5;
    const int lane = tid & 31;

    // ---- phase 0: halo tiles (float4, mh tf32-rounded) + raw sr tile ----
    #pragma unroll
    for (int k = 0; k < 4; k++) {
        const int idx = tid + k*NT;
        if (idx < HALO_H*34) {
            const int r  = idx / 34, c4 = idx % 34;
            const int y  = y0 + r, x = x0 + c4*4;
            float4 m4 = make_float4(0.f,0.f,0.f,0.f);
            float4 h4 = make_float4(0.f,0.f,0.f,0.f);
            if (y < H && x + 3 < H) {
                m4 = *(const float4*)&mb[y*H + x];
                h4 = *(const float4*)&hb[y*H + x];
                if (c4 == 33) { m4.z = 0.f; m4.w = 0.f; }
            }
            float4 l4;
            l4.x = __uint_as_float(f2tf32(m4.x*h4.x));
            l4.y = __uint_as_float(f2tf32(m4.y*h4.y));
            l4.z = __uint_as_float(f2tf32(m4.z*h4.z));
            l4.w = __uint_as_float(f2tf32(m4.w*h4.w));
            *(float4*)&s_m [r*HALO_W + c4*4] = m4;
            *(float4*)&s_mh[r*HALO_W + c4*4] = l4;
        }
    }
    #pragma unroll
    for (int k = 0; k < 12; k++) {
        const int idx = tid + k*NT;
        const int r = idx >> 7, c = idx & 127;
        const int y = y0 + r, x = x0 + c;
        float v = 0.f;
        if (y < CROP && x < CROP)
            v = sb[(y+BORDER)*H + (x+BORDER)];
        s_p[r*SP_STRIDE + c] = v;
    }
    __syncthreads();

    // ---- fused box partials from owned 24x128 region (tf32-consistent) ----
    for (int r = wid; r < TY; r += 8) {
        const float4 m4 = *(const float4*)&s_m [r*HALO_W + lane*4];
        const float4 l4 = *(const float4*)&s_mh[r*HALO_W + lane*4];
        float sm = m4.x + m4.y + m4.z + m4.w;
        float sl = l4.x + l4.y + l4.z + l4.w;
        float sh = l4.x*l4.x + l4.y*l4.y + l4.z*l4.z + l4.w*l4.w;
        #pragma unroll
        for (int off = 16; off; off >>= 1) {
            sm += __shfl_xor_sync(0xffffffffu, sm, off);
            sl += __shfl_xor_sync(0xffffffffu, sl, off);
            sh += __shfl_xor_sync(0xffffffffu, sh, off);
        }
        if (lane == 0) {
            float* q = g_rsum + (((size_t)batch*H + (y0+r))*3 + bxi)*3;
            q[0] = sm; q[1] = sl; q[2] = sh;
        }
    }
    if (bxi == 0 && tid < TY*6) {
        const int r = tid / 6, c = tid % 6;
        const float m = s_m[r*HALO_W + c], l = s_mh[r*HALO_W + c];
        float* q = g_eL + ((size_t)batch*H + (y0+r))*18;
        q[0*6+c] = m; q[1*6+c] = l; q[2*6+c] = l*l;
    }
    if (bxi == 2 && tid < TY*6) {
        const int r = tid / 6, c = tid % 6;
        const float m = s_m[r*HALO_W + 122 + c], l = s_mh[r*HALO_W + 122 + c];
        float* q = g_eR + ((size_t)batch*H + (y0+r))*18;
        q[0*6+c] = m; q[1*6+c] = l; q[2*6+c] = l*l;
    }

    // ---- mask-multiply pred tile; tf32-round; accumulate sum(pred) ----
    float tp = 0.f;
    #pragma unroll
    for (int k = 0; k < 12; k++) {
        const int idx = tid + k*NT;
        const int r = idx >> 7, c = idx & 127;
        const float p = s_p[r*SP_STRIDE + c] * s_m[(r+BORDER)*HALO_W + (c+BORDER)];
        s_p[r*SP_STRIDE + c] = __uint_as_float(f2tf32(p));
        tp += p;
    }
    #pragma unroll
    for (int off = 16; off; off >>= 1)
        tp += __shfl_xor_sync(0xffffffffu, tp, off);
    if (lane == 0) s_red[wid] = tp;
    __syncthreads();
    if (tid == 0) {
        float s = 0.f;
        #pragma unroll
        for (int k = 0; k < 8; k++) s += s_red[k];
        g_ppart[(size_t)batch*NTILE + byi*GX + bxi] = s;
    }

    // ---- tensor mainloop: warp wid owns x-chunks {2wid, 2wid+1} ----
    // A rows: 0-6 = mh (j=row), 7-13 = m (j=row-7), 14-15 zero.
    // B cols: i = 0..6 (col 7 garbage, ignored). K = 8 pred columns.
    const int g  = lane >> 2;        // 0..7
    const int t4 = lane & 3;
    const float* pA0 = ((g < 7) ? (s_mh + g) : s_m) + t4;   // row g
    const float* pA1 = s_m + (g + 1) + t4;                  // row g+8 (j=g+1)
    const bool  v1   = (g < 6);                              // rows 14,15 -> 0
    const float* pB  = s_p + t4;

    float C1[4] = {0.f,0.f,0.f,0.f};   // {hp rows, mp rows} x i
    float C2[4] = {0.f,0.f,0.f,0.f};   // pp rows (7-13) x i

    #pragma unroll
    for (int xcl = 0; xcl < 2; xcl++) {
        const int xc8 = (wid*2 + xcl) << 3;
        #pragma unroll 3
        for (int yw = 0; yw < HALO_H; yw++) {
            const int wb = yw*HALO_W + xc8;
            const uint32 a0 = __float_as_uint(pA0[wb]);
            const uint32 a2 = __float_as_uint(pA0[wb+4]);
            const uint32 a1 = v1 ? __float_as_uint(pA1[wb])   : 0u;
            const uint32 a3 = v1 ? __float_as_uint(pA1[wb+4]) : 0u;
            const int pr  = yw - g;
            const bool vb = ((unsigned)pr < (unsigned)TY);
            const int pra = vb ? pr : 0;
            const int ob  = pra*SP_STRIDE + xc8;
            float bv0 = pB[ob];
            float bv1 = pB[ob+4];
            bv0 = vb ? bv0 : 0.f;
            bv1 = vb ? bv1 : 0.f;
            mma_tf32(C1, a0, a1, a2, a3,
                     __float_as_uint(bv0), __float_as_uint(bv1));
            const uint32 q0 = f2tf32(bv0*bv0);
            const uint32 q1 = f2tf32(bv1*bv1);
            mma_tf32(C2, a0, a1, a2, a3, q0, q1);
        }
    }

    // ---- fragment extraction -> smem -> fixed-order 8-warp reduce ----
    __syncthreads();                 // s_m/s_mh/s_p dead; reuse dyn
    float* sp1 = dyn;                // [8 warps][16 rows][8 cols]
    float* sp2 = dyn + 1024;
    {
        const int cb2 = 2*t4;
        float* d1 = sp1 + wid*128;
        float* d2 = sp2 + wid*128;
        d1[g*8 + cb2]       = C1[0];
        d1[g*8 + cb2 + 1]   = C1[1];
        d1[(g+8)*8 + cb2]   = C1[2];
        d1[(g+8)*8 + cb2+1] = C1[3];
        d2[g*8 + cb2]       = C2[0];
        d2[g*8 + cb2 + 1]   = C2[1];
        d2[(g+8)*8 + cb2]   = C2[2];
        d2[(g+8)*8 + cb2+1] = C2[3];
    }
    __syncthreads();
    {
        const int tile = byi*GX + bxi;
        for (int t = tid; t < 147; t += NT) {
            const int comp = t / 49, s = t % 49;
            const int i = s / 7, j = s % 7;
            const int row = (comp == 0) ? j : (7 + j);
            const float* src = (comp == 1) ? sp2 : sp1;
            float v = 0.f;
            #pragma unroll
            for (int w = 0; w < 8; w++) v += src[w*128 + row*8 + i];
            g_part[(((size_t)batch*NSH + s)*3 + comp)*NTILE + tile] = v;
        }
    }

    // ======== per-batch finalizer election ========
    __syncthreads();
    if (tid == 0) {
        __threadfence();
        if (atomicAdd(&g_bctr[batch], 1) == NTILE - 1) {
            s_flag[0] = 1;
            g_bctr[batch] = 0;
        } else s_flag[0] = 0;
    }
    __syncthreads();
    if (!s_flag[0]) return;

    // ======== mse finalization (overlaid on dyn; prior data flushed) ========
    float (*sA)[9]     = (float(*)[9])   (dyn + 2048);
    float (*sL)[18]    = (float(*)[18])  (dyn + 2048 + 216);
    float (*sR)[18]    = (float(*)[18])  (dyn + 2048 + 432);
    float  *Tq         =                  dyn + 2048 + 648;
    float  *GL         =                  dyn + 2048 + 657;
    float  *GR         =                  dyn + 2048 + 675;
    float (*eRaw)[45]  = (float(*)[45])  (dyn + 2048 + 693);
    float (*e_w)[3][7] = (float(*)[3][7])(dyn + 2048 + 1233);
    float (*ctot)[7]   = (float(*)[7])   (dyn + 2048 + 1485);
    float  *ssp        =                  dyn + 2048 + 1506;
    float  *s_mse      =                  dyn + 2048 + 1507;

    const int b = batch;
    __threadfence();

    if (tid < 216) {
        {   const int c = tid % 9, gg = tid / 9;
            float acc = 0.f;
            const float* base = g_rsum + (size_t)b*H*9;
            for (int y = gg; y < H; y += 24) acc += base[y*9 + c];
            sA[gg][c] = acc;
        }
        {   const int c = tid % 18, gg = tid / 18;
            float aL = 0.f, aR = 0.f;
            const float* bl = g_eL + (size_t)b*H*18;
            const float* br = g_eR + (size_t)b*H*18;
            for (int y = gg; y < H; y += 12) { aL += bl[y*18 + c]; aR += br[y*18 + c]; }
            sL[gg][c] = aL; sR[gg][c] = aR;
        }
    }
    for (int t = tid; t < 12*45; t += NT) {
        const int r = t / 45, c = t % 45;
        const int y = (r < 6) ? r : (372 + r);
        float v;
        if (c < 9)       v = g_rsum[((size_t)b*H + y)*9 + c];
        else if (c < 27) v = g_eL [((size_t)b*H + y)*18 + (c-9)];
        else             v = g_eR [((size_t)b*H + y)*18 + (c-27)];
        eRaw[r][c] = v;
    }
    if (wid == 7) {
        const float* q = g_ppart + (size_t)b*NTILE;
        float c = q[lane] + ((lane < NTILE-32) ? q[lane+32] : 0.f);
        #pragma unroll
        for (int off = 16; off; off >>= 1)
            c += __shfl_xor_sync(0xffffffffu, c, off);
        if (lane == 0) *ssp = c;
    }
    __syncthreads();

    if (tid < 9)       { float s=0.f; for (int gg=0; gg<24; gg++) s += sA[gg][tid];    Tq[tid] = s; }
    else if (tid < 27) { const int c=tid-9;  float s=0.f; for (int gg=0; gg<12; gg++) s += sL[gg][c]; GL[c] = s; }
    else if (tid < 45) { const int c=tid-27; float s=0.f; for (int gg=0; gg<12; gg++) s += sR[gg][c]; GR[c] = s; }
    __syncthreads();

    if (tid < 21) {
        const int f = tid / 7, j = tid % 7;
        float T = Tq[f] + Tq[3+f] + Tq[6+f];
        for (int k = 0; k < j; k++) T -= GL[f*6 + k];
        for (int k = j; k < 6; k++) T -= GR[f*6 + k];
        ctot[f][j] = T;
    }
    for (int t = tid; t < 252; t += NT) {
        const int r = t / 21, rest = t % 21;
        const int f = rest / 7, j = rest % 7;
        float T = eRaw[r][f] + eRaw[r][3+f] + eRaw[r][6+f];
        for (int k = 0; k < j; k++) T -= eRaw[r][9  + f*6 + k];
        for (int k = j; k < 6; k++) T -= eRaw[r][27 + f*6 + k];
        e_w[r][f][j] = T;
    }
    if (tid >= NSH && tid < 64) s_mse[tid] = 3.4e38f;
    __syncthreads();

    if (wid < 7) {
        #pragma unroll
        for (int q = 0; q < 7; q++) {
            const int s = wid*7 + q;
            float comp[3];
            #pragma unroll
            for (int c = 0; c < 3; c++) {
                const float* base = g_part + (((size_t)b*NSH + s)*3 + c)*NTILE;
                float v = base[lane] + ((lane < NTILE-32) ? base[lane+32] : 0.f);
                #pragma unroll
                for (int off = 16; off; off >>= 1)
                    v += __shfl_xor_sync(0xffffffffu, v, off);
                comp[c] = v;
            }
            if (lane == 0) {
                const int i = s / 7, jc = s % 7;
                float Sm  = ctot[0][jc];
                float SL  = ctot[1][jc];
                float Shh = ctot[2][jc];
                for (int y = 0; y < i; y++) {
                    Sm -= e_w[y][0][jc]; SL -= e_w[y][1][jc]; Shh -= e_w[y][2][jc];
                }
                for (int t = i + 6; t < 12; t++) {
                    Sm -= e_w[t][0][jc]; SL -= e_w[t][1][jc]; Shh -= e_w[t][2][jc];
                }
                const float hp = comp[0], pp = comp[1], mp = comp[2];
                const float bias = (SL - *ssp) / Sm;
                const float num  = Shh - 2.f*hp + pp - 2.f*bias*(SL - mp) + bias*bias*Sm;
                s_mse[s] = num / Sm;
            }
        }
    }
    __syncthreads();

    #pragma unroll
    for (int off = 32; off; off >>= 1) {
        if (tid < off) s_mse[tid] = fminf(s_mse[tid], s_mse[tid + off]);
        __syncthreads();
    }
    if (tid == 0) {
        g_bmin[b] = s_mse[0];
        __threadfence();
        if (atomicAdd(&g_ctr, 1) == Bn - 1) { s_flag[1] = 1; g_ctr = 0; }
        else s_flag[1] = 0;
    }
    __syncthreads();

    if (s_flag[1]) {
        __threadfence();
        if (tid < 64) s_mse[tid] = g_bmin[tid];
        __syncthreads();
        #pragma unroll
        for (int off = 32; off; off >>= 1) {
            if (tid < off) s_mse[tid] += s_mse[tid + off];
            __syncthreads();
        }
        if (tid == 0) out[0] = s_mse[0] * (1.f / (float)Bn);
    }
}

extern "C" void kernel_launch(void* const* d_in, const int* in_sizes, int n_in,
                              void* d_out, int out_size)
{
    const float* sr = (const float*)d_in[0];
    const float* hr = (const float*)d_in[1];
    const float* mk = (const float*)d_in[2];
    (void)in_sizes; (void)n_in; (void)out_size;

    cudaFuncSetAttribute(corr_kernel,
                         cudaFuncAttributeMaxDynamicSharedMemorySize, DYN_BYTES);
    corr_kernel<<<dim3(GX, GY, Bn), NT, DYN_BYTES>>>(sr, hr, mk, (float*)d_out);
}

// round 16
// speedup vs baseline: 1.5166x; 1.0748x over previous
#include <cuda_runtime.h>

#define Bn 64
#define H  384
#define HH (H*H)
#define BORDER 3
#define CROP 378
#define NSH 49

// corr tiling: 3 x 16 tiles exactly partition 384 x 384 (owned 128 x 24 each)
#define TX 128
#define TY 24
#define GX 3
#define GY 16
#define NTILE (GX*GY)   // 48
#define HALO_W 136      // need 134, pad to 136
#define HALO_H 30       // TY + 6
#define NT 256          // 8 warps

#define MH_ELEMS (HALO_H*HALO_W)          // 4080
#define SP_STRIDE 132                     // bank-spread: (7-g)*132+t4 covers 32 banks
#define SP_ROWS 37                        // 7 zero + 24 data + 6 zero
#define SP_ELEMS (SP_ROWS*SP_STRIDE)      // 4884
#define SP_PADTOP 7
#define DYN_FLOATS (2*MH_ELEMS + SP_ELEMS) // 13044
#define DYN_BYTES (DYN_FLOATS*4)          // 52176

typedef unsigned int uint32;

// scratch (static device memory; zero-initialized; no allocations anywhere)
__device__ float g_part [Bn*NSH*3*NTILE];   // corr partials: [b][shift][comp][tile]
__device__ float g_rsum [Bn*H*3*3];         // per (b,y,bx): {Sm,SL,Shh} partial
__device__ float g_eL   [Bn*H*3*6];         // left edge cols 0..5 per field
__device__ float g_eR   [Bn*H*3*6];         // right edge cols 378..383 per field
__device__ float g_ppart[Bn*NTILE];         // per-tile sum of pred
__device__ float g_bmin [Bn];               // per-batch min cMSE
__device__ int   g_bctr [Bn];               // per-batch tile counter (self-resets)
__device__ int   g_ctr;                     // global batch counter (self-resets)

__device__ __forceinline__ uint32 f2tf32(float x) {
    uint32 r; asm("cvt.rna.tf32.f32 %0, %1;" : "=r"(r) : "f"(x)); return r;
}
__device__ __forceinline__ void mma_tf32(float c[4], uint32 a0, uint32 a1,
                                         uint32 a2, uint32 a3, uint32 b0, uint32 b1) {
    asm volatile("mma.sync.aligned.m16n8k8.row.col.f32.tf32.tf32.f32 "
        "{%0,%1,%2,%3}, {%4,%5,%6,%7}, {%8,%9}, {%0,%1,%2,%3};"
        : "+f"(c[0]), "+f"(c[1]), "+f"(c[2]), "+f"(c[3])
        : "r"(a0), "r"(a1), "r"(a2), "r"(a3), "r"(b0), "r"(b1));
}

// ---------------------------------------------------------------------------
// corr_kernel: 7x7 correlations via tf32 tensor MMA + fused box partials;
// last block per batch runs mse finalization; overall-last writes out[0].
// Mainloop ALU-stripped: zero-padded pred tile (no B predicates), immediate
// LDS offsets via 5x6 unrolled pointer-increment loop.
// ---------------------------------------------------------------------------
__global__ __launch_bounds__(NT, 4) void corr_kernel(
    const float* __restrict__ sr, const float* __restrict__ hr,
    const float* __restrict__ mk, float* __restrict__ out)
{
    extern __shared__ __align__(16) float dyn[];
    float* s_m  = dyn;                          // [HALO_H][HALO_W]
    float* s_mh = dyn + MH_ELEMS;               // [HALO_H][HALO_W] (tf32)
    float* s_p  = dyn + 2*MH_ELEMS;             // [SP_ROWS][SP_STRIDE] padded
    float* s_pd = s_p + SP_PADTOP*SP_STRIDE;    // data rows 0..23

    __shared__ float s_red[8];
    __shared__ int   s_flag[2];

    const int batch = blockIdx.z;
    const int bxi = blockIdx.x, byi = blockIdx.y;
    const int x0 = bxi * TX;
    const int y0 = byi * TY;
    const float* mb = mk + (size_t)batch*HH;
    const float* hb = hr + (size_t)batch*HH;
    const float* sb = sr + (size_t)batch*HH;
    const int tid  = threadIdx.x;
    const int wid  = tid >> 5;
    const int lane = tid & 31;

    // ---- phase 0: halo tiles + raw sr tile + zero pad rows, one sync ----
    #pragma unroll
    for (int k = 0; k < 4; k++) {
        const int idx = tid + k*NT;
        if (idx < HALO_H*34) {
            const int r  = idx / 34, c4 = idx % 34;
            const int y  = y0 + r, x = x0 + c4*4;
            float4 m4 = make_float4(0.f,0.f,0.f,0.f);
            float4 h4 = make_float4(0.f,0.f,0.f,0.f);
            if (y < H && x + 3 < H) {
                m4 = *(const float4*)&mb[y*H + x];
                h4 = *(const float4*)&hb[y*H + x];
                if (c4 == 33) { m4.z = 0.f; m4.w = 0.f; }
            }
            float4 l4;
            l4.x = __uint_as_float(f2tf32(m4.x*h4.x));
            l4.y = __uint_as_float(f2tf32(m4.y*h4.y));
            l4.z = __uint_as_float(f2tf32(m4.z*h4.z));
            l4.w = __uint_as_float(f2tf32(m4.w*h4.w));
            *(float4*)&s_m [r*HALO_W + c4*4] = m4;
            *(float4*)&s_mh[r*HALO_W + c4*4] = l4;
        }
    }
    #pragma unroll
    for (int k = 0; k < 12; k++) {
        const int idx = tid + k*NT;
        const int r = idx >> 7, c = idx & 127;
        const int y = y0 + r, x = x0 + c;
        float v = 0.f;
        if (y < CROP && x < CROP)
            v = sb[(y+BORDER)*H + (x+BORDER)];
        s_pd[r*SP_STRIDE + c] = v;
    }
    // zero pad rows (7 top, 6 bottom): 13*132 = 1716 elems
    #pragma unroll
    for (int k = 0; k < 7; k++) {
        const int idx = tid + k*NT;
        if (idx < 13*SP_STRIDE) {
            const int pr13 = idx / SP_STRIDE, c = idx % SP_STRIDE;
            const int row = (pr13 < 7) ? pr13 : (24 + pr13);   // 0..6 | 31..36
            s_p[row*SP_STRIDE + c] = 0.f;
        }
    }
    __syncthreads();

    // ---- fused box partials from owned 24x128 region (tf32-consistent) ----
    for (int r = wid; r < TY; r += 8) {
        const float4 m4 = *(const float4*)&s_m [r*HALO_W + lane*4];
        const float4 l4 = *(const float4*)&s_mh[r*HALO_W + lane*4];
        float sm = m4.x + m4.y + m4.z + m4.w;
        float sl = l4.x + l4.y + l4.z + l4.w;
        float sh = l4.x*l4.x + l4.y*l4.y + l4.z*l4.z + l4.w*l4.w;
        #pragma unroll
        for (int off = 16; off; off >>= 1) {
            sm += __shfl_xor_sync(0xffffffffu, sm, off);
            sl += __shfl_xor_sync(0xffffffffu, sl, off);
            sh += __shfl_xor_sync(0xffffffffu, sh, off);
        }
        if (lane == 0) {
            float* q = g_rsum + (((size_t)batch*H + (y0+r))*3 + bxi)*3;
            q[0] = sm; q[1] = sl; q[2] = sh;
        }
    }
    if (bxi == 0 && tid < TY*6) {
        const int r = tid / 6, c = tid % 6;
        const float m = s_m[r*HALO_W + c], l = s_mh[r*HALO_W + c];
        float* q = g_eL + ((size_t)batch*H + (y0+r))*18;
        q[0*6+c] = m; q[1*6+c] = l; q[2*6+c] = l*l;
    }
    if (bxi == 2 && tid < TY*6) {
        const int r = tid / 6, c = tid % 6;
        const float m = s_m[r*HALO_W + 122 + c], l = s_mh[r*HALO_W + 122 + c];
        float* q = g_eR + ((size_t)batch*H + (y0+r))*18;
        q[0*6+c] = m; q[1*6+c] = l; q[2*6+c] = l*l;
    }

    // ---- mask-multiply pred tile; tf32-round; accumulate sum(pred) ----
    float tp = 0.f;
    #pragma unroll
    for (int k = 0; k < 12; k++) {
        const int idx = tid + k*NT;
        const int r = idx >> 7, c = idx & 127;
        const float p = s_pd[r*SP_STRIDE + c] * s_m[(r+BORDER)*HALO_W + (c+BORDER)];
        s_pd[r*SP_STRIDE + c] = __uint_as_float(f2tf32(p));
        tp += p;
    }
    #pragma unroll
    for (int off = 16; off; off >>= 1)
        tp += __shfl_xor_sync(0xffffffffu, tp, off);
    if (lane == 0) s_red[wid] = tp;
    __syncthreads();
    if (tid == 0) {
        float s = 0.f;
        #pragma unroll
        for (int k = 0; k < 8; k++) s += s_red[k];
        g_ppart[(size_t)batch*NTILE + byi*GX + bxi] = s;
    }

    // ---- tensor mainloop: warp wid owns x-chunks {2wid, 2wid+1} ----
    // A rows: 0-6 = mh (j=row), 7-13 = m (j=row-7), 14-15 zero (v1 select).
    // B: p(yw-g, xc+k) read from padded tile -> no predicates.
    const int g  = lane >> 2;        // 0..7
    const int t4 = lane & 3;
    const float* pA0base = ((g < 7) ? (s_mh + g) : s_m) + t4;
    const float* pA1base = s_m + (g + 1) + t4;
    const bool  v1 = (g < 6);
    const float* pBbase  = s_p + (SP_PADTOP - g)*SP_STRIDE + t4;

    float C1[4] = {0.f,0.f,0.f,0.f};
    float C2[4] = {0.f,0.f,0.f,0.f};

    #pragma unroll
    for (int xcl = 0; xcl < 2; xcl++) {
        const int xc8 = (wid*2 + xcl) << 3;
        const float* pa0 = pA0base + xc8;
        const float* pa1 = pA1base + xc8;
        const float* pb  = pBbase  + xc8;
        #pragma unroll
        for (int blk = 0; blk < 5; blk++) {
            #pragma unroll
            for (int k = 0; k < 6; k++) {
                const int wo = k*HALO_W;
                const int po = k*SP_STRIDE;
                const uint32 a0 = __float_as_uint(pa0[wo]);
                const uint32 a2 = __float_as_uint(pa0[wo+4]);
                const uint32 a1 = v1 ? __float_as_uint(pa1[wo])   : 0u;
                const uint32 a3 = v1 ? __float_as_uint(pa1[wo+4]) : 0u;
                const float bv0 = pb[po];
                const float bv1 = pb[po+4];
                mma_tf32(C1, a0, a1, a2, a3,
                         __float_as_uint(bv0), __float_as_uint(bv1));
                mma_tf32(C2, a0, a1, a2, a3, f2tf32(bv0*bv0), f2tf32(bv1*bv1));
            }
            pa0 += 6*HALO_W; pa1 += 6*HALO_W; pb += 6*SP_STRIDE;
        }
    }

    // ---- fragment extraction -> smem -> fixed-order 8-warp reduce ----
    __syncthreads();                 // tiles dead; reuse dyn
    float* sp1 = dyn;                // [8 warps][16 rows][8 cols]
    float* sp2 = dyn + 1024;
    {
        const int cb2 = 2*t4;
        float* d1 = sp1 + wid*128;
        float* d2 = sp2 + wid*128;
        d1[g*8 + cb2]       = C1[0];
        d1[g*8 + cb2 + 1]   = C1[1];
        d1[(g+8)*8 + cb2]   = C1[2];
        d1[(g+8)*8 + cb2+1] = C1[3];
        d2[g*8 + cb2]       = C2[0];
        d2[g*8 + cb2 + 1]   = C2[1];
        d2[(g+8)*8 + cb2]   = C2[2];
        d2[(g+8)*8 + cb2+1] = C2[3];
    }
    __syncthreads();
    {
        const int tile = byi*GX + bxi;
        for (int t = tid; t < 147; t += NT) {
            const int comp = t / 49, s = t % 49;
            const int i = s / 7, j = s % 7;
            const int row = (comp == 0) ? j : (7 + j);
            const float* src = (comp == 1) ? sp2 : sp1;
            float v = 0.f;
            #pragma unroll
            for (int w = 0; w < 8; w++) v += src[w*128 + row*8 + i];
            g_part[(((size_t)batch*NSH + s)*3 + comp)*NTILE + tile] = v;
        }
    }

    // ======== per-batch finalizer election ========
    __syncthreads();
    if (tid == 0) {
        __threadfence();
        if (atomicAdd(&g_bctr[batch], 1) == NTILE - 1) {
            s_flag[0] = 1;
            g_bctr[batch] = 0;
        } else s_flag[0] = 0;
    }
    __syncthreads();
    if (!s_flag[0]) return;

    // ======== mse finalization (overlaid on dyn; prior data flushed) ========
    float (*sA)[9]     = (float(*)[9])   (dyn + 2048);
    float (*sL)[18]    = (float(*)[18])  (dyn + 2048 + 216);
    float (*sR)[18]    = (float(*)[18])  (dyn + 2048 + 432);
    float  *Tq         =                  dyn + 2048 + 648;
    float  *GL         =                  dyn + 2048 + 657;
    float  *GR         =                  dyn + 2048 + 675;
    float (*eRaw)[45]  = (float(*)[45])  (dyn + 2048 + 693);
    float (*e_w)[3][7] = (float(*)[3][7])(dyn + 2048 + 1233);
    float (*ctot)[7]   = (float(*)[7])   (dyn + 2048 + 1485);
    float  *ssp        =                  dyn + 2048 + 1506;
    float  *s_mse      =                  dyn + 2048 + 1507;

    const int b = batch;
    __threadfence();

    if (tid < 216) {
        {   const int c = tid % 9, gg = tid / 9;
            float acc = 0.f;
            const float* base = g_rsum + (size_t)b*H*9;
            for (int y = gg; y < H; y += 24) acc += base[y*9 + c];
            sA[gg][c] = acc;
        }
        {   const int c = tid % 18, gg = tid / 18;
            float aL = 0.f, aR = 0.f;
            const float* bl = g_eL + (size_t)b*H*18;
            const float* br = g_eR + (size_t)b*H*18;
            for (int y = gg; y < H; y += 12) { aL += bl[y*18 + c]; aR += br[y*18 + c]; }
            sL[gg][c] = aL; sR[gg][c] = aR;
        }
    }
    for (int t = tid; t < 12*45; t += NT) {
        const int r = t / 45, c = t % 45;
        const int y = (r < 6) ? r : (372 + r);
        float v;
        if (c < 9)       v = g_rsum[((size_t)b*H + y)*9 + c];
        else if (c < 27) v = g_eL [((size_t)b*H + y)*18 + (c-9)];
        else             v = g_eR [((size_t)b*H + y)*18 + (c-27)];
        eRaw[r][c] = v;
    }
    if (wid == 7) {
        const float* q = g_ppart + (size_t)b*NTILE;
        float c = q[lane] + ((lane < NTILE-32) ? q[lane+32] : 0.f);
        #pragma unroll
        for (int off = 16; off; off >>= 1)
            c += __shfl_xor_sync(0xffffffffu, c, off);
        if (lane == 0) *ssp = c;
    }
    __syncthreads();

    if (tid < 9)       { float s=0.f; for (int gg=0; gg<24; gg++) s += sA[gg][tid];    Tq[tid] = s; }
    else if (tid < 27) { const int c=tid-9;  float s=0.f; for (int gg=0; gg<12; gg++) s += sL[gg][c]; GL[c] = s; }
    else if (tid < 45) { const int c=tid-27; float s=0.f; for (int gg=0; gg<12; gg++) s += sR[gg][c]; GR[c] = s; }
    __syncthreads();

    if (tid < 21) {
        const int f = tid / 7, j = tid % 7;
        float T = Tq[f] + Tq[3+f] + Tq[6+f];
        for (int k = 0; k < j; k++) T -= GL[f*6 + k];
        for (int k = j; k < 6; k++) T -= GR[f*6 + k];
        ctot[f][j] = T;
    }
    for (int t = tid; t < 252; t += NT) {
        const int r = t / 21, rest = t % 21;
        const int f = rest / 7, j = rest % 7;
        float T = eRaw[r][f] + eRaw[r][3+f] + eRaw[r][6+f];
        for (int k = 0; k < j; k++) T -= eRaw[r][9  + f*6 + k];
        for (int k = j; k < 6; k++) T -= eRaw[r][27 + f*6 + k];
        e_w[r][f][j] = T;
    }
    if (tid >= NSH && tid < 64) s_mse[tid] = 3.4e38f;
    __syncthreads();

    if (wid < 7) {
        #pragma unroll
        for (int q = 0; q < 7; q++) {
            const int s = wid*7 + q;
            float comp[3];
            #pragma unroll
            for (int c = 0; c < 3; c++) {
                const float* base = g_part + (((size_t)b*NSH + s)*3 + c)*NTILE;
                float v = base[lane] + ((lane < NTILE-32) ? base[lane+32] : 0.f);
                #pragma unroll
                for (int off = 16; off; off >>= 1)
                    v += __shfl_xor_sync(0xffffffffu, v, off);
                comp[c] = v;
            }
            if (lane == 0) {
                const int i = s / 7, jc = s % 7;
                float Sm  = ctot[0][jc];
                float SL  = ctot[1][jc];
                float Shh = ctot[2][jc];
                for (int y = 0; y < i; y++) {
                    Sm -= e_w[y][0][jc]; SL -= e_w[y][1][jc]; Shh -= e_w[y][2][jc];
                }
                for (int t = i + 6; t < 12; t++) {
                    Sm -= e_w[t][0][jc]; SL -= e_w[t][1][jc]; Shh -= e_w[t][2][jc];
                }
                const float hp = comp[0], pp = comp[1], mp = comp[2];
                const float bias = (SL - *ssp) / Sm;
                const float num  = Shh - 2.f*hp + pp - 2.f*bias*(SL - mp) + bias*bias*Sm;
                s_mse[s] = num / Sm;
            }
        }
    }
    __syncthreads();

    #pragma unroll
    for (int off = 32; off; off >>= 1) {
        if (tid < off) s_mse[tid] = fminf(s_mse[tid], s_mse[tid + off]);
        __syncthreads();
    }
    if (tid == 0) {
        g_bmin[b] = s_mse[0];
        __threadfence();
        if (atomicAdd(&g_ctr, 1) == Bn - 1) { s_flag[1] = 1; g_ctr = 0; }
        else s_flag[1] = 0;
    }
    __syncthreads();

    if (s_flag[1]) {
        __threadfence();
        if (tid < 64) s_mse[tid] = g_bmin[tid];
        __syncthreads();
        #pragma unroll
        for (int off = 32; off; off >>= 1) {
            if (tid < off) s_mse[tid] += s_mse[tid + off];
            __syncthreads();
        }
        if (tid == 0) out[0] = s_mse[0] * (1.f / (float)Bn);
    }
}

extern "C" void kernel_launch(void* const* d_in, const int* in_sizes, int n_in,
                              void* d_out, int out_size)
{
    const float* sr = (const float*)d_in[0];
    const float* hr = (const float*)d_in[1];
    const float* mk = (const float*)d_in[2];
    (void)in_sizes; (void)n_in; (void)out_size;

    cudaFuncSetAttribute(corr_kernel,
                         cudaFuncAttributeMaxDynamicSharedMemorySize, DYN_BYTES);
    corr_kernel<<<dim3(GX, GY, Bn), NT, DYN_BYTES>>>(sr, hr, mk, (float*)d_out);
}

// round 17
// speedup vs baseline: 1.5185x; 1.0013x over previous
#include <cuda_runtime.h>

#define Bn 64
#define H  384
#define HH (H*H)
#define BORDER 3
#define CROP 378
#define NSH 49

// corr tiling: 3 x 16 tiles exactly partition 384 x 384 (owned 128 x 24 each)
#define TX 128
#define TY 24
#define GX 3
#define GY 16
#define NTILE (GX*GY)   // 48
#define HALO_W 136      // need 134, pad to 136
#define HALO_H 30       // TY + 6
#define NT 256          // 8 warps

#define MH_ELEMS (HALO_H*HALO_W)          // 4080
#define SP_STRIDE 132                     // bank-spread: (7-g)*132+t4 covers 32 banks
#define SP_ROWS 37                        // 7 zero + 24 data + 6 zero
#define SP_ELEMS (SP_ROWS*SP_STRIDE)      // 4884
#define SP_PADTOP 7
#define DYN_FLOATS (2*MH_ELEMS + SP_ELEMS) // 13044
#define DYN_BYTES (DYN_FLOATS*4)          // 52176

typedef unsigned int uint32;

// scratch (static device memory; zero-initialized; no allocations anywhere)
__device__ float g_part [Bn*NSH*3*NTILE];   // corr partials: [b][shift][comp][tile]
__device__ float g_rsum [Bn*H*3*3];         // per (b,y,bx): {Sm,SL,Shh} partial
__device__ float g_eL   [Bn*H*3*6];         // left edge cols 0..5 per field
__device__ float g_eR   [Bn*H*3*6];         // right edge cols 378..383 per field
__device__ float g_ppart[Bn*NTILE];         // per-tile sum of pred
__device__ float g_bmin [Bn];               // per-batch min cMSE
__device__ int   g_bctr [Bn];               // per-batch tile counter (self-resets)
__device__ int   g_ctr;                     // global batch counter (self-resets)

__device__ __forceinline__ uint32 f2tf32(float x) {
    uint32 r; asm("cvt.rna.tf32.f32 %0, %1;" : "=r"(r) : "f"(x)); return r;
}
__device__ __forceinline__ void mma_tf32(float c[4], uint32 a0, uint32 a1,
                                         uint32 a2, uint32 a3, uint32 b0, uint32 b1) {
    asm volatile("mma.sync.aligned.m16n8k8.row.col.f32.tf32.tf32.f32 "
        "{%0,%1,%2,%3}, {%4,%5,%6,%7}, {%8,%9}, {%0,%1,%2,%3};"
        : "+f"(c[0]), "+f"(c[1]), "+f"(c[2]), "+f"(c[3])
        : "r"(a0), "r"(a1), "r"(a2), "r"(a3), "r"(b0), "r"(b1));
}

// ---------------------------------------------------------------------------
// corr_kernel: 7x7 correlations via tf32 tensor MMA + fused box partials;
// last block per batch runs mse finalization; overall-last writes out[0].
// Mainloop ALU-stripped: zero-padded pred tile (no B predicates), immediate
// LDS offsets via 5x6 unrolled pointer-increment loop.
// ---------------------------------------------------------------------------
__global__ __launch_bounds__(NT, 4) void corr_kernel(
    const float* __restrict__ sr, const float* __restrict__ hr,
    const float* __restrict__ mk, float* __restrict__ out)
{
    extern __shared__ __align__(16) float dyn[];
    float* s_m  = dyn;                          // [HALO_H][HALO_W]
    float* s_mh = dyn + MH_ELEMS;               // [HALO_H][HALO_W] (tf32)
    float* s_p  = dyn + 2*MH_ELEMS;             // [SP_ROWS][SP_STRIDE] padded
    float* s_pd = s_p + SP_PADTOP*SP_STRIDE;    // data rows 0..23

    __shared__ float s_red[8];
    __shared__ int   s_flag[2];

    const int batch = blockIdx.z;
    const int bxi = blockIdx.x, byi = blockIdx.y;
    const int x0 = bxi * TX;
    const int y0 = byi * TY;
    const float* mb = mk + (size_t)batch*HH;
    const float* hb = hr + (size_t)batch*HH;
    const float* sb = sr + (size_t)batch*HH;
    const int tid  = threadIdx.x;
    const int wid  = tid >> 5;
    const int lane = tid & 31;

    // ---- phase 0: halo tiles + raw sr tile + zero pad rows, one sync ----
    #pragma unroll
    for (int k = 0; k < 4; k++) {
        const int idx = tid + k*NT;
        if (idx < HALO_H*34) {
            const int r  = idx / 34, c4 = idx % 34;
            const int y  = y0 + r, x = x0 + c4*4;
            float4 m4 = make_float4(0.f,0.f,0.f,0.f);
            float4 h4 = make_float4(0.f,0.f,0.f,0.f);
            if (y < H && x + 3 < H) {
                m4 = *(const float4*)&mb[y*H + x];
                h4 = *(const float4*)&hb[y*H + x];
                if (c4 == 33) { m4.z = 0.f; m4.w = 0.f; }
            }
            float4 l4;
            l4.x = __uint_as_float(f2tf32(m4.x*h4.x));
            l4.y = __uint_as_float(f2tf32(m4.y*h4.y));
            l4.z = __uint_as_float(f2tf32(m4.z*h4.z));
            l4.w = __uint_as_float(f2tf32(m4.w*h4.w));
            *(float4*)&s_m [r*HALO_W + c4*4] = m4;
            *(float4*)&s_mh[r*HALO_W + c4*4] = l4;
        }
    }
    #pragma unroll
    for (int k = 0; k < 12; k++) {
        const int idx = tid + k*NT;
        const int r = idx >> 7, c = idx & 127;
        const int y = y0 + r, x = x0 + c;
        float v = 0.f;
        if (y < CROP && x < CROP)
            v = sb[(y+BORDER)*H + (x+BORDER)];
        s_pd[r*SP_STRIDE + c] = v;
    }
    // zero pad rows (7 top, 6 bottom): 13*132 = 1716 elems
    #pragma unroll
    for (int k = 0; k < 7; k++) {
        const int idx = tid + k*NT;
        if (idx < 13*SP_STRIDE) {
            const int pr13 = idx / SP_STRIDE, c = idx % SP_STRIDE;
            const int row = (pr13 < 7) ? pr13 : (24 + pr13);   // 0..6 | 31..36
            s_p[row*SP_STRIDE + c] = 0.f;
        }
    }
    __syncthreads();

    // ---- fused box partials from owned 24x128 region (tf32-consistent) ----
    for (int r = wid; r < TY; r += 8) {
        const float4 m4 = *(const float4*)&s_m [r*HALO_W + lane*4];
        const float4 l4 = *(const float4*)&s_mh[r*HALO_W + lane*4];
        float sm = m4.x + m4.y + m4.z + m4.w;
        float sl = l4.x + l4.y + l4.z + l4.w;
        float sh = l4.x*l4.x + l4.y*l4.y + l4.z*l4.z + l4.w*l4.w;
        #pragma unroll
        for (int off = 16; off; off >>= 1) {
            sm += __shfl_xor_sync(0xffffffffu, sm, off);
            sl += __shfl_xor_sync(0xffffffffu, sl, off);
            sh += __shfl_xor_sync(0xffffffffu, sh, off);
        }
        if (lane == 0) {
            float* q = g_rsum + (((size_t)batch*H + (y0+r))*3 + bxi)*3;
            q[0] = sm; q[1] = sl; q[2] = sh;
        }
    }
    if (bxi == 0 && tid < TY*6) {
        const int r = tid / 6, c = tid % 6;
        const float m = s_m[r*HALO_W + c], l = s_mh[r*HALO_W + c];
        float* q = g_eL + ((size_t)batch*H + (y0+r))*18;
        q[0*6+c] = m; q[1*6+c] = l; q[2*6+c] = l*l;
    }
    if (bxi == 2 && tid < TY*6) {
        const int r = tid / 6, c = tid % 6;
        const float m = s_m[r*HALO_W + 122 + c], l = s_mh[r*HALO_W + 122 + c];
        float* q = g_eR + ((size_t)batch*H + (y0+r))*18;
        q[0*6+c] = m; q[1*6+c] = l; q[2*6+c] = l*l;
    }

    // ---- mask-multiply pred tile; tf32-round; accumulate sum(pred) ----
    float tp = 0.f;
    #pragma unroll
    for (int k = 0; k < 12; k++) {
        const int idx = tid + k*NT;
        const int r = idx >> 7, c = idx & 127;
        const float p = s_pd[r*SP_STRIDE + c] * s_m[(r+BORDER)*HALO_W + (c+BORDER)];
        s_pd[r*SP_STRIDE + c] = __uint_as_float(f2tf32(p));
        tp += p;
    }
    #pragma unroll
    for (int off = 16; off; off >>= 1)
        tp += __shfl_xor_sync(0xffffffffu, tp, off);
    if (lane == 0) s_red[wid] = tp;
    __syncthreads();
    if (tid == 0) {
        float s = 0.f;
        #pragma unroll
        for (int k = 0; k < 8; k++) s += s_red[k];
        g_ppart[(size_t)batch*NTILE + byi*GX + bxi] = s;
    }

    // ---- tensor mainloop: warp wid owns x-chunks {2wid, 2wid+1} ----
    // A rows: 0-6 = mh (j=row), 7-13 = m (j=row-7), 14-15 zero (v1 select).
    // B: p(yw-g, xc+k) read from padded tile -> no predicates.
    const int g  = lane >> 2;        // 0..7
    const int t4 = lane & 3;
    const float* pA0base = ((g < 7) ? (s_mh + g) : s_m) + t4;
    const float* pA1base = s_m + (g + 1) + t4;
    const bool  v1 = (g < 6);
    const float* pBbase  = s_p + (SP_PADTOP - g)*SP_STRIDE + t4;

    float C1[4] = {0.f,0.f,0.f,0.f};
    float C2[4] = {0.f,0.f,0.f,0.f};

    #pragma unroll
    for (int xcl = 0; xcl < 2; xcl++) {
        const int xc8 = (wid*2 + xcl) << 3;
        const float* pa0 = pA0base + xc8;
        const float* pa1 = pA1base + xc8;
        const float* pb  = pBbase  + xc8;
        #pragma unroll
        for (int blk = 0; blk < 5; blk++) {
            #pragma unroll
            for (int k = 0; k < 6; k++) {
                const int wo = k*HALO_W;
                const int po = k*SP_STRIDE;
                const uint32 a0 = __float_as_uint(pa0[wo]);
                const uint32 a2 = __float_as_uint(pa0[wo+4]);
                const uint32 a1 = v1 ? __float_as_uint(pa1[wo])   : 0u;
                const uint32 a3 = v1 ? __float_as_uint(pa1[wo+4]) : 0u;
                const float bv0 = pb[po];
                const float bv1 = pb[po+4];
                mma_tf32(C1, a0, a1, a2, a3,
                         __float_as_uint(bv0), __float_as_uint(bv1));
                mma_tf32(C2, a0, a1, a2, a3, f2tf32(bv0*bv0), f2tf32(bv1*bv1));
            }
            pa0 += 6*HALO_W; pa1 += 6*HALO_W; pb += 6*SP_STRIDE;
        }
    }

    // ---- fragment extraction -> smem -> fixed-order 8-warp reduce ----
    __syncthreads();                 // tiles dead; reuse dyn
    float* sp1 = dyn;                // [8 warps][16 rows][8 cols]
    float* sp2 = dyn + 1024;
    {
        const int cb2 = 2*t4;
        float* d1 = sp1 + wid*128;
        float* d2 = sp2 + wid*128;
        d1[g*8 + cb2]       = C1[0];
        d1[g*8 + cb2 + 1]   = C1[1];
        d1[(g+8)*8 + cb2]   = C1[2];
        d1[(g+8)*8 + cb2+1] = C1[3];
        d2[g*8 + cb2]       = C2[0];
        d2[g*8 + cb2 + 1]   = C2[1];
        d2[(g+8)*8 + cb2]   = C2[2];
        d2[(g+8)*8 + cb2+1] = C2[3];
    }
    __syncthreads();
    {
        const int tile = byi*GX + bxi;
        for (int t = tid; t < 147; t += NT) {
            const int comp = t / 49, s = t % 49;
            const int i = s / 7, j = s % 7;
            const int row = (comp == 0) ? j : (7 + j);
            const float* src = (comp == 1) ? sp2 : sp1;
            float v = 0.f;
            #pragma unroll
            for (int w = 0; w < 8; w++) v += src[w*128 + row*8 + i];
            g_part[(((size_t)batch*NSH + s)*3 + comp)*NTILE + tile] = v;
        }
    }

    // ======== per-batch finalizer election ========
    __syncthreads();
    if (tid == 0) {
        __threadfence();
        if (atomicAdd(&g_bctr[batch], 1) == NTILE - 1) {
            s_flag[0] = 1;
            g_bctr[batch] = 0;
        } else s_flag[0] = 0;
    }
    __syncthreads();
    if (!s_flag[0]) return;

    // ======== mse finalization (overlaid on dyn; prior data flushed) ========
    float (*sA)[9]     = (float(*)[9])   (dyn + 2048);
    float (*sL)[18]    = (float(*)[18])  (dyn + 2048 + 216);
    float (*sR)[18]    = (float(*)[18])  (dyn + 2048 + 432);
    float  *Tq         =                  dyn + 2048 + 648;
    float  *GL         =                  dyn + 2048 + 657;
    float  *GR         =                  dyn + 2048 + 675;
    float (*eRaw)[45]  = (float(*)[45])  (dyn + 2048 + 693);
    float (*e_w)[3][7] = (float(*)[3][7])(dyn + 2048 + 1233);
    float (*ctot)[7]   = (float(*)[7])   (dyn + 2048 + 1485);
    float  *ssp        =                  dyn + 2048 + 1506;
    float  *s_mse      =                  dyn + 2048 + 1507;

    const int b = batch;
    __threadfence();

    if (tid < 216) {
        {   const int c = tid % 9, gg = tid / 9;
            float acc = 0.f;
            const float* base = g_rsum + (size_t)b*H*9;
            for (int y = gg; y < H; y += 24) acc += base[y*9 + c];
            sA[gg][c] = acc;
        }
        {   const int c = tid % 18, gg = tid / 18;
            float aL = 0.f, aR = 0.f;
            const float* bl = g_eL + (size_t)b*H*18;
            const float* br = g_eR + (size_t)b*H*18;
            for (int y = gg; y < H; y += 12) { aL += bl[y*18 + c]; aR += br[y*18 + c]; }
            sL[gg][c] = aL; sR[gg][c] = aR;
        }
    }
    for (int t = tid; t < 12*45; t += NT) {
        const int r = t / 45, c = t % 45;
        const int y = (r < 6) ? r : (372 + r);
        float v;
        if (c < 9)       v = g_rsum[((size_t)b*H + y)*9 + c];
        else if (c < 27) v = g_eL [((size_t)b*H + y)*18 + (c-9)];
        else             v = g_eR [((size_t)b*H + y)*18 + (c-27)];
        eRaw[r][c] = v;
    }
    if (wid == 7) {
        const float* q = g_ppart + (size_t)b*NTILE;
        float c = q[lane] + ((lane < NTILE-32) ? q[lane+32] : 0.f);
        #pragma unroll
        for (int off = 16; off; off >>= 1)
            c += __shfl_xor_sync(0xffffffffu, c, off);
        if (lane == 0) *ssp = c;
    }
    __syncthreads();

    if (tid < 9)       { float s=0.f; for (int gg=0; gg<24; gg++) s += sA[gg][tid];    Tq[tid] = s; }
    else if (tid < 27) { const int c=tid-9;  float s=0.f; for (int gg=0; gg<12; gg++) s += sL[gg][c]; GL[c] = s; }
    else if (tid < 45) { const int c=tid-27; float s=0.f; for (int gg=0; gg<12; gg++) s += sR[gg][c]; GR[c] = s; }
    __syncthreads();

    if (tid < 21) {
        const int f = tid / 7, j = tid % 7;
        float T = Tq[f] + Tq[3+f] + Tq[6+f];
        for (int k = 0; k < j; k++) T -= GL[f*6 + k];
        for (int k = j; k < 6; k++) T -= GR[f*6 + k];
        ctot[f][j] = T;
    }
    for (int t = tid; t < 252; t += NT) {
        const int r = t / 21, rest = t % 21;
        const int f = rest / 7, j = rest % 7;
        float T = eRaw[r][f] + eRaw[r][3+f] + eRaw[r][6+f];
        for (int k = 0; k < j; k++) T -= eRaw[r][9  + f*6 + k];
        for (int k = j; k < 6; k++) T -= eRaw[r][27 + f*6 + k];
        e_w[r][f][j] = T;
    }
    if (tid >= NSH && tid < 64) s_mse[tid] = 3.4e38f;
    __syncthreads();

    if (wid < 7) {
        #pragma unroll
        for (int q = 0; q < 7; q++) {
            const int s = wid*7 + q;
            float comp[3];
            #pragma unroll
            for (int c = 0; c < 3; c++) {
                const float* base = g_part + (((size_t)b*NSH + s)*3 + c)*NTILE;
                float v = base[lane] + ((lane < NTILE-32) ? base[lane+32] : 0.f);
                #pragma unroll
                for (int off = 16; off; off >>= 1)
                    v += __shfl_xor_sync(0xffffffffu, v, off);
                comp[c] = v;
            }
            if (lane == 0) {
                const int i = s / 7, jc = s % 7;
                float Sm  = ctot[0][jc];
                float SL  = ctot[1][jc];
                float Shh = ctot[2][jc];
                for (int y = 0; y < i; y++) {
                    Sm -= e_w[y][0][jc]; SL -= e_w[y][1][jc]; Shh -= e_w[y][2][jc];
                }
                for (int t = i + 6; t < 12; t++) {
                    Sm -= e_w[t][0][jc]; SL -= e_w[t][1][jc]; Shh -= e_w[t][2][jc];
                }
                const float hp = comp[0], pp = comp[1], mp = comp[2];
                const float bias = (SL - *ssp) / Sm;
                const float num  = Shh - 2.f*hp + pp - 2.f*bias*(SL - mp) + bias*bias*Sm;
                s_mse[s] = num / Sm;
            }
        }
    }
    __syncthreads();

    #pragma unroll
    for (int off = 32; off; off >>= 1) {
        if (tid < off) s_mse[tid] = fminf(s_mse[tid], s_mse[tid + off]);
        __syncthreads();
    }
    if (tid == 0) {
        g_bmin[b] = s_mse[0];
        __threadfence();
        if (atomicAdd(&g_ctr, 1) == Bn - 1) { s_flag[1] = 1; g_ctr = 0; }
        else s_flag[1] = 0;
    }
    __syncthreads();

    if (s_flag[1]) {
        __threadfence();
        if (tid < 64) s_mse[tid] = g_bmin[tid];
        __syncthreads();
        #pragma unroll
        for (int off = 32; off; off >>= 1) {
            if (tid < off) s_mse[tid] += s_mse[tid + off];
            __syncthreads();
        }
        if (tid == 0) out[0] = s_mse[0] * (1.f / (float)Bn);
    }
}

extern "C" void kernel_launch(void* const* d_in, const int* in_sizes, int n_in,
                              void* d_out, int out_size)
{
    const float* sr = (const float*)d_in[0];
    const float* hr = (const float*)d_in[1];
    const float* mk = (const float*)d_in[2];
    (void)in_sizes; (void)n_in; (void)out_size;

    cudaFuncSetAttribute(corr_kernel,
                         cudaFuncAttributeMaxDynamicSharedMemorySize, DYN_BYTES);
    corr_kernel<<<dim3(GX, GY, Bn), NT, DYN_BYTES>>>(sr, hr, mk, (float*)d_out);
}